// round 2
// baseline (speedup 1.0000x reference)
#include <cuda_runtime.h>
#include <cuda_bf16.h>

// Problem constants
#define B_   4
#define S_   2048
#define D_   1024
#define H_   16
#define DH_  64
#define M_   (B_ * S_)       // 8192
#define NQKV (3 * D_)        // 3072

// Scratch (allocation-free rule: __device__ globals)
// Q,K,V laid out [B,H,S,DH]; O laid out [B,S,H,DH] (== GEMM3 A matrix row-major)
__device__ float g_Q[B_ * H_ * S_ * DH_];
__device__ float g_K[B_ * H_ * S_ * DH_];
__device__ float g_V[B_ * H_ * S_ * DH_];
__device__ float g_O[B_ * S_ * H_ * DH_];

// ---------------------------------------------------------------------------
// Kernel 1: qkv = x @ w_qkv + b_qkv, scatter into g_Q/g_K/g_V as [B,H,S,DH]
// A: [M_, 1024] row-major (x). W: [1024, 3072] row-major (w_qkv flattened).
// 128x128 tile, BK=8, 256 threads, 8x8 per thread.
// ---------------------------------------------------------------------------
__global__ __launch_bounds__(256, 2) void qkv_gemm_kernel(
    const float* __restrict__ A, const float* __restrict__ W,
    const float* __restrict__ bias) {
  const int K = D_;
  const int N = NQKV;
  __shared__ float As[8][128];
  __shared__ float Bs[8][128];
  const int tid = threadIdx.x;
  const int tx = tid & 15, ty = tid >> 4;
  const int m0 = blockIdx.y * 128;
  const int n0 = blockIdx.x * 128;

  float acc[8][8];
#pragma unroll
  for (int i = 0; i < 8; i++)
#pragma unroll
    for (int j = 0; j < 8; j++) acc[i][j] = 0.f;

  const int aRow = tid >> 1, aCol = (tid & 1) << 2;
  const int bRow = tid >> 5, bCol = (tid & 31) << 2;
  const float* Ap = A + (m0 + aRow) * K + aCol;
  const float* Wp = W + bRow * N + n0 + bCol;

  for (int k0 = 0; k0 < K; k0 += 8) {
    const float4 av = *(const float4*)(Ap + k0);
    const float4 bv = *(const float4*)(Wp + k0 * N);
    __syncthreads();
    As[aCol + 0][aRow] = av.x;
    As[aCol + 1][aRow] = av.y;
    As[aCol + 2][aRow] = av.z;
    As[aCol + 3][aRow] = av.w;
    *(float4*)&Bs[bRow][bCol] = bv;
    __syncthreads();
#pragma unroll
    for (int kk = 0; kk < 8; kk++) {
      float ar[8], br[8];
      *(float4*)&ar[0] = *(const float4*)&As[kk][ty * 8];
      *(float4*)&ar[4] = *(const float4*)&As[kk][ty * 8 + 4];
      *(float4*)&br[0] = *(const float4*)&Bs[kk][tx * 8];
      *(float4*)&br[4] = *(const float4*)&Bs[kk][tx * 8 + 4];
#pragma unroll
      for (int i = 0; i < 8; i++)
#pragma unroll
        for (int j = 0; j < 8; j++) acc[i][j] += ar[i] * br[j];
    }
  }

  // Epilogue: column block n..n+7 stays inside one (t,h) since n0+tx*8 is a
  // multiple of 8 and DH_=64 boundaries are multiples of 8.
  const int nb = n0 + tx * 8;
  const int t = nb >> 10;         // 0=q 1=k 2=v
  const int rem = nb & 1023;
  const int h = rem >> 6;
  const int e0 = rem & 63;
  float* dst = (t == 0) ? g_Q : (t == 1) ? g_K : g_V;
  const float4 bz0 = *(const float4*)&bias[nb];
  const float4 bz1 = *(const float4*)&bias[nb + 4];
#pragma unroll
  for (int ii = 0; ii < 8; ii++) {
    const int m = m0 + ty * 8 + ii;
    const int b = m >> 11;        // S_=2048
    const int s = m & 2047;
    float4 o0, o1;
    o0.x = acc[ii][0] + bz0.x; o0.y = acc[ii][1] + bz0.y;
    o0.z = acc[ii][2] + bz0.z; o0.w = acc[ii][3] + bz0.w;
    o1.x = acc[ii][4] + bz1.x; o1.y = acc[ii][5] + bz1.y;
    o1.z = acc[ii][6] + bz1.z; o1.w = acc[ii][7] + bz1.w;
    float* p = dst + (((b * H_ + h) * S_ + s) * DH_ + e0);
    *(float4*)p = o0;
    *(float4*)(p + 4) = o1;
  }
}

// ---------------------------------------------------------------------------
// Kernel 2: causal flash attention, fp32. One block = 64 q-rows of one (b,h).
// Q^T and K^T in smem (transposed so fragment reads are contiguous LDS.128).
// P tile reuses the K smem buffer -> static smem exactly 48 KB.
// ---------------------------------------------------------------------------
__global__ __launch_bounds__(256, 2) void attn_kernel() {
  __shared__ float QsT[64][64];   // QsT[e][i]
  __shared__ float KPs[64][64];   // phase 1: K^T[e][j]; phase 2: P[i][j]
  __shared__ float Vs[64][64];    // Vs[j][e]

  const int tid = threadIdx.x;
  const int tx = tid & 15, ty = tid >> 4;
  const int qt = blockIdx.x;
  const int bh = blockIdx.y;
  const int q0 = qt * 64;
  const int b = bh >> 4, h = bh & 15;

  const float* Qb = g_Q + (size_t)bh * S_ * DH_;
  const float* Kb = g_K + (size_t)bh * S_ * DH_;
  const float* Vb = g_V + (size_t)bh * S_ * DH_;

  // Load Q tile transposed. Lanes vary j -> conflict-free transposed stores.
#pragma unroll
  for (int it = 0; it < 4; it++) {
    const int idx = tid + it * 256;
    const int j = idx & 63, e4 = idx >> 6;
    const float4 v = *(const float4*)&Qb[(q0 + j) * DH_ + e4 * 4];
    QsT[e4 * 4 + 0][j] = v.x;
    QsT[e4 * 4 + 1][j] = v.y;
    QsT[e4 * 4 + 2][j] = v.z;
    QsT[e4 * 4 + 3][j] = v.w;
  }

  const int i0 = ty * 4;          // score rows / O rows
  const int j0 = tx * 4;          // score cols
  const int e0 = tx * 4;          // O cols (DH)

  float m_i[4], l_i[4], o[4][4];
#pragma unroll
  for (int i = 0; i < 4; i++) {
    m_i[i] = -1e30f;
    l_i[i] = 0.f;
#pragma unroll
    for (int e = 0; e < 4; e++) o[i][e] = 0.f;
  }

  for (int kt = 0; kt <= qt; kt++) {
    const int k0 = kt * 64;
    __syncthreads();  // prior-iter PV reads done (and first-iter Q stores done)
#pragma unroll
    for (int it = 0; it < 4; it++) {
      const int idx = tid + it * 256;
      const int j = idx & 63, e4 = idx >> 6;
      const float4 v = *(const float4*)&Kb[(k0 + j) * DH_ + e4 * 4];
      KPs[e4 * 4 + 0][j] = v.x;
      KPs[e4 * 4 + 1][j] = v.y;
      KPs[e4 * 4 + 2][j] = v.z;
      KPs[e4 * 4 + 3][j] = v.w;
      const int r = idx >> 4, c = (idx & 15) * 4;
      *(float4*)&Vs[r][c] = *(const float4*)&Vb[(k0 + r) * DH_ + c];
    }
    __syncthreads();

    // S = Q K^T * 0.125
    float s[4][4];
#pragma unroll
    for (int i = 0; i < 4; i++)
#pragma unroll
      for (int j = 0; j < 4; j++) s[i][j] = 0.f;

#pragma unroll 8
    for (int e = 0; e < 64; e++) {
      const float4 qv = *(const float4*)&QsT[e][i0];
      const float4 kv = *(const float4*)&KPs[e][j0];
      const float qa[4] = {qv.x, qv.y, qv.z, qv.w};
      const float ka[4] = {kv.x, kv.y, kv.z, kv.w};
#pragma unroll
      for (int i = 0; i < 4; i++)
#pragma unroll
        for (int j = 0; j < 4; j++) s[i][j] += qa[i] * ka[j];
    }
#pragma unroll
    for (int i = 0; i < 4; i++)
#pragma unroll
      for (int j = 0; j < 4; j++) s[i][j] *= 0.125f;

    if (kt == qt) {  // diagonal tile: causal mask (k0 == q0)
#pragma unroll
      for (int i = 0; i < 4; i++)
#pragma unroll
        for (int j = 0; j < 4; j++)
          if (j0 + j > i0 + i) s[i][j] = -1e30f;
    }

    // Online softmax update (row groups are 16-lane shfl groups)
#pragma unroll
    for (int i = 0; i < 4; i++) {
      float mx = fmaxf(fmaxf(s[i][0], s[i][1]), fmaxf(s[i][2], s[i][3]));
#pragma unroll
      for (int off = 8; off; off >>= 1)
        mx = fmaxf(mx, __shfl_xor_sync(0xffffffffu, mx, off));
      const float mnew = fmaxf(m_i[i], mx);
      const float sc = __expf(m_i[i] - mnew);
      float rs = 0.f;
#pragma unroll
      for (int j = 0; j < 4; j++) {
        s[i][j] = __expf(s[i][j] - mnew);
        rs += s[i][j];
      }
#pragma unroll
      for (int off = 8; off; off >>= 1)
        rs += __shfl_xor_sync(0xffffffffu, rs, off);
      l_i[i] = l_i[i] * sc + rs;
      m_i[i] = mnew;
#pragma unroll
      for (int e = 0; e < 4; e++) o[i][e] *= sc;
    }

    __syncthreads();  // everyone done reading K^T from KPs
#pragma unroll
    for (int i = 0; i < 4; i++)
      *(float4*)&KPs[i0 + i][j0] = make_float4(s[i][0], s[i][1], s[i][2], s[i][3]);
    __syncthreads();

    // O += P @ V
#pragma unroll 8
    for (int j = 0; j < 64; j++) {
      const float4 vv = *(const float4*)&Vs[j][e0];
      const float va[4] = {vv.x, vv.y, vv.z, vv.w};
      float pr[4];
#pragma unroll
      for (int i = 0; i < 4; i++) pr[i] = KPs[i0 + i][j];
#pragma unroll
      for (int i = 0; i < 4; i++)
#pragma unroll
        for (int e = 0; e < 4; e++) o[i][e] += pr[i] * va[e];
    }
  }

  // Epilogue: normalize and store to g_O as [B,S,H,DH]
#pragma unroll
  for (int i = 0; i < 4; i++) {
    const float inv = 1.f / l_i[i];
    const int srow = q0 + i0 + i;
    const float4 ov = make_float4(o[i][0] * inv, o[i][1] * inv,
                                  o[i][2] * inv, o[i][3] * inv);
    *(float4*)&g_O[(((size_t)(b * S_ + srow)) * H_ + h) * DH_ + e0] = ov;
  }
}

// ---------------------------------------------------------------------------
// Kernel 3: out = O @ w_out + b_out.
// A: g_O [M_, 1024] row-major. W: w_out flattened [1024, 1024] row-major.
// ---------------------------------------------------------------------------
__global__ __launch_bounds__(256, 2) void out_gemm_kernel(
    const float* __restrict__ W, const float* __restrict__ bias,
    float* __restrict__ out) {
  const int K = H_ * DH_;   // 1024
  const int N = D_;         // 1024
  __shared__ float As[8][128];
  __shared__ float Bs[8][128];
  const int tid = threadIdx.x;
  const int tx = tid & 15, ty = tid >> 4;
  const int m0 = blockIdx.y * 128;
  const int n0 = blockIdx.x * 128;

  float acc[8][8];
#pragma unroll
  for (int i = 0; i < 8; i++)
#pragma unroll
    for (int j = 0; j < 8; j++) acc[i][j] = 0.f;

  const int aRow = tid >> 1, aCol = (tid & 1) << 2;
  const int bRow = tid >> 5, bCol = (tid & 31) << 2;
  const float* Ap = g_O + (m0 + aRow) * K + aCol;
  const float* Wp = W + bRow * N + n0 + bCol;

  for (int k0 = 0; k0 < K; k0 += 8) {
    const float4 av = *(const float4*)(Ap + k0);
    const float4 bv = *(const float4*)(Wp + k0 * N);
    __syncthreads();
    As[aCol + 0][aRow] = av.x;
    As[aCol + 1][aRow] = av.y;
    As[aCol + 2][aRow] = av.z;
    As[aCol + 3][aRow] = av.w;
    *(float4*)&Bs[bRow][bCol] = bv;
    __syncthreads();
#pragma unroll
    for (int kk = 0; kk < 8; kk++) {
      float ar[8], br[8];
      *(float4*)&ar[0] = *(const float4*)&As[kk][ty * 8];
      *(float4*)&ar[4] = *(const float4*)&As[kk][ty * 8 + 4];
      *(float4*)&br[0] = *(const float4*)&Bs[kk][tx * 8];
      *(float4*)&br[4] = *(const float4*)&Bs[kk][tx * 8 + 4];
#pragma unroll
      for (int i = 0; i < 8; i++)
#pragma unroll
        for (int j = 0; j < 8; j++) acc[i][j] += ar[i] * br[j];
    }
  }

  const int nb = n0 + tx * 8;
  const float4 bz0 = *(const float4*)&bias[nb];
  const float4 bz1 = *(const float4*)&bias[nb + 4];
#pragma unroll
  for (int ii = 0; ii < 8; ii++) {
    const int m = m0 + ty * 8 + ii;
    float4 o0, o1;
    o0.x = acc[ii][0] + bz0.x; o0.y = acc[ii][1] + bz0.y;
    o0.z = acc[ii][2] + bz0.z; o0.w = acc[ii][3] + bz0.w;
    o1.x = acc[ii][4] + bz1.x; o1.y = acc[ii][5] + bz1.y;
    o1.z = acc[ii][6] + bz1.z; o1.w = acc[ii][7] + bz1.w;
    float* p = out + (size_t)m * N + nb;
    *(float4*)p = o0;
    *(float4*)(p + 4) = o1;
  }
}

// ---------------------------------------------------------------------------
extern "C" void kernel_launch(void* const* d_in, const int* in_sizes, int n_in,
                              void* d_out, int out_size) {
  const float* x     = (const float*)d_in[0];  // [B,S,D]
  const float* w_qkv = (const float*)d_in[1];  // [D,3,H,DH]
  const float* b_qkv = (const float*)d_in[2];  // [3,H,DH]
  const float* w_out = (const float*)d_in[3];  // [H,DH,D]
  const float* b_out = (const float*)d_in[4];  // [D]
  float* out = (float*)d_out;                  // [B,S,D]

  qkv_gemm_kernel<<<dim3(NQKV / 128, M_ / 128), 256>>>(x, w_qkv, b_qkv);
  attn_kernel<<<dim3(S_ / 64, B_ * H_), 256>>>();
  out_gemm_kernel<<<dim3(D_ / 128, M_ / 128), 256>>>(w_out, b_out, out);
}

// round 4
// speedup vs baseline: 1.1692x; 1.1692x over previous
#include <cuda_runtime.h>
#include <cuda_bf16.h>
#include <cstdint>

// Problem constants
#define B_   4
#define S_   2048
#define D_   1024
#define H_   16
#define DH_  64
#define M_   (B_ * S_)       // 8192
#define NQKV (3 * D_)        // 3072

// GEMM tiling
#define BM 128
#define BN 128
#define BKT 16
#define ASTRIDE 20   // BKT + 4 pad (floats); 80B rows, 16B aligned, ldmatrix conflict-free
#define BSTRIDE 136  // BN + 8 pad (floats); B-frag scalar loads hit 32 distinct banks

// Scratch (allocation-free rule: __device__ globals)
__device__ float g_Q[B_ * H_ * S_ * DH_];
__device__ float g_K[B_ * H_ * S_ * DH_];
__device__ float g_V[B_ * H_ * S_ * DH_];
__device__ float g_O[B_ * S_ * H_ * DH_];

__device__ __forceinline__ uint32_t smem_u32(const void* p) {
  return (uint32_t)__cvta_generic_to_shared(p);
}

__device__ __forceinline__ void cp_async16(uint32_t dst, const void* src) {
  asm volatile("cp.async.cg.shared.global [%0], [%1], 16;\n" ::"r"(dst), "l"(src));
}
__device__ __forceinline__ void cp_commit() {
  asm volatile("cp.async.commit_group;\n");
}
template <int N>
__device__ __forceinline__ void cp_wait() {
  asm volatile("cp.async.wait_group %0;\n" ::"n"(N));
}

__device__ __forceinline__ void ldmatrix_x4(uint32_t* r, uint32_t addr) {
  asm volatile(
      "ldmatrix.sync.aligned.m8n8.x4.shared.b16 {%0,%1,%2,%3}, [%4];\n"
      : "=r"(r[0]), "=r"(r[1]), "=r"(r[2]), "=r"(r[3])
      : "r"(addr));
}

__device__ __forceinline__ void mma_tf32(float* c, const uint32_t* a,
                                         uint32_t b0, uint32_t b1) {
  asm volatile(
      "mma.sync.aligned.m16n8k8.row.col.f32.tf32.tf32.f32 "
      "{%0,%1,%2,%3}, {%4,%5,%6,%7}, {%8,%9}, {%0,%1,%2,%3};\n"
      : "+f"(c[0]), "+f"(c[1]), "+f"(c[2]), "+f"(c[3])
      : "r"(a[0]), "r"(a[1]), "r"(a[2]), "r"(a[3]), "r"(b0), "r"(b1));
}

// 3xTF32 split: f = hi + lo with hi = rna_tf32(f), lo = rna_tf32(f - hi).
__device__ __forceinline__ void split_tf32(uint32_t fbits, uint32_t& hi,
                                           uint32_t& lo) {
  const float f = __uint_as_float(fbits);
  uint32_t h;
  asm("cvt.rna.tf32.f32 %0, %1;\n" : "=r"(h) : "f"(f));
  const float r = f - __uint_as_float(h);
  asm("cvt.rna.tf32.f32 %0, %1;\n" : "=r"(lo) : "f"(r));
  hi = h;
}

// ---------------------------------------------------------------------------
// Shared tf32x3 mma mainloop: computes acc[4][4][4] for a 128x128 C tile with
// ~fp32 accuracy. A: [M][K] row-major, Wm: [K][N] row-major.
// ---------------------------------------------------------------------------
struct MmaCtx {
  float acc[4][4][4];
};

template <int K, int N>
__device__ __forceinline__ void tf32_mainloop(
    const float* __restrict__ A, const float* __restrict__ Wm,
    int m0, int n0, float (*As)[BM * ASTRIDE], float (*Bs)[BKT * BSTRIDE],
    MmaCtx& ctx) {
  const int tid = threadIdx.x;
  const int lane = tid & 31;
  const int wid = tid >> 5;
  const int wm = wid & 1;   // 0..1  (64-row slabs)
  const int wn = wid >> 1;  // 0..3  (32-col slabs)

#pragma unroll
  for (int mt = 0; mt < 4; mt++)
#pragma unroll
    for (int nt = 0; nt < 4; nt++)
#pragma unroll
      for (int r = 0; r < 4; r++) ctx.acc[mt][nt][r] = 0.f;

  const int kTiles = K / BKT;

  const int acr0 = tid >> 2, akc0 = tid & 3;
  const int acr1 = (tid + 256) >> 2, akc1 = tid & 3;
  const int bk0 = tid >> 5, bnc = tid & 31;
  const int bk1 = (tid + 256) >> 5;

  auto load_tile = [&](int t, int buf) {
    const int k0 = t * BKT;
    cp_async16(smem_u32(&As[buf][acr0 * ASTRIDE + akc0 * 4]),
               A + (size_t)(m0 + acr0) * K + k0 + akc0 * 4);
    cp_async16(smem_u32(&As[buf][acr1 * ASTRIDE + akc1 * 4]),
               A + (size_t)(m0 + acr1) * K + k0 + akc1 * 4);
    cp_async16(smem_u32(&Bs[buf][bk0 * BSTRIDE + bnc * 4]),
               Wm + (size_t)(k0 + bk0) * N + n0 + bnc * 4);
    cp_async16(smem_u32(&Bs[buf][bk1 * BSTRIDE + bnc * 4]),
               Wm + (size_t)(k0 + bk1) * N + n0 + bnc * 4);
    cp_commit();
  };

  load_tile(0, 0);

  const int lrow = (lane & 7) + ((lane >> 3) & 1) * 8;
  const int lcol = ((lane >> 4) & 1) * 4;

  for (int t = 0; t < kTiles; t++) {
    const int buf = t & 1;
    if (t + 1 < kTiles) {
      load_tile(t + 1, (t + 1) & 1);
      cp_wait<1>();
    } else {
      cp_wait<0>();
    }
    __syncthreads();

#pragma unroll
    for (int ks = 0; ks < 2; ks++) {
      uint32_t ahi[4][4], alo[4][4];
#pragma unroll
      for (int mt = 0; mt < 4; mt++) {
        uint32_t af[4];
        const int row = wm * 64 + mt * 16 + lrow;
        ldmatrix_x4(af, smem_u32(&As[buf][row * ASTRIDE + ks * 8 + lcol]));
#pragma unroll
        for (int r = 0; r < 4; r++) split_tf32(af[r], ahi[mt][r], alo[mt][r]);
      }
      uint32_t bhi[4][2], blo[4][2];
#pragma unroll
      for (int nt = 0; nt < 4; nt++) {
        const int col = wn * 32 + nt * 8 + (lane >> 2);
        const int kr = ks * 8 + (lane & 3);
        split_tf32(__float_as_uint(Bs[buf][kr * BSTRIDE + col]),
                   bhi[nt][0], blo[nt][0]);
        split_tf32(__float_as_uint(Bs[buf][(kr + 4) * BSTRIDE + col]),
                   bhi[nt][1], blo[nt][1]);
      }
      // 3xTF32: small terms first, then the big one.
#pragma unroll
      for (int mt = 0; mt < 4; mt++)
#pragma unroll
        for (int nt = 0; nt < 4; nt++) {
          mma_tf32(ctx.acc[mt][nt], alo[mt], bhi[nt][0], bhi[nt][1]);
          mma_tf32(ctx.acc[mt][nt], ahi[mt], blo[nt][0], blo[nt][1]);
          mma_tf32(ctx.acc[mt][nt], ahi[mt], bhi[nt][0], bhi[nt][1]);
        }
    }
    __syncthreads();
  }
}

// ---------------------------------------------------------------------------
// Kernel 1: qkv = x @ w_qkv + b_qkv -> scatter to g_Q/g_K/g_V as [B,H,S,DH]
// ---------------------------------------------------------------------------
__global__ __launch_bounds__(256, 1) void qkv_gemm_kernel(
    const float* __restrict__ A, const float* __restrict__ W,
    const float* __restrict__ bias) {
  __shared__ float As[2][BM * ASTRIDE];
  __shared__ float Bs[2][BKT * BSTRIDE];
  const int m0 = blockIdx.y * BM;
  const int n0 = blockIdx.x * BN;

  MmaCtx ctx;
  tf32_mainloop<D_, NQKV>(A, W, m0, n0, As, Bs, ctx);

  const int lane = threadIdx.x & 31;
  const int wid = threadIdx.x >> 5;
  const int wm = wid & 1, wn = wid >> 1;

#pragma unroll
  for (int nt = 0; nt < 4; nt++) {
    const int n = n0 + wn * 32 + nt * 8 + (lane & 3) * 2;
    const int t = n >> 10;
    const int rem = n & 1023;
    const int h = rem >> 6;
    const int e = rem & 63;
    float* dst = (t == 0) ? g_Q : (t == 1) ? g_K : g_V;
    const float bz0 = bias[n], bz1 = bias[n + 1];
#pragma unroll
    for (int mt = 0; mt < 4; mt++) {
      const int mbase = m0 + wm * 64 + mt * 16 + (lane >> 2);
#pragma unroll
      for (int half = 0; half < 2; half++) {
        const int m = mbase + half * 8;
        const int b = m >> 11;
        const int s = m & 2047;
        float2 v;
        v.x = ctx.acc[mt][nt][half * 2 + 0] + bz0;
        v.y = ctx.acc[mt][nt][half * 2 + 1] + bz1;
        *(float2*)&dst[(((b * H_ + h) * S_ + s) * DH_) + e] = v;
      }
    }
  }
}

// ---------------------------------------------------------------------------
// Kernel 3: out = g_O @ w_out + b_out   (g_O [M][1024], W [1024][1024])
// ---------------------------------------------------------------------------
__global__ __launch_bounds__(256, 1) void out_gemm_kernel(
    const float* __restrict__ W, const float* __restrict__ bias,
    float* __restrict__ out) {
  __shared__ float As[2][BM * ASTRIDE];
  __shared__ float Bs[2][BKT * BSTRIDE];
  const int m0 = blockIdx.y * BM;
  const int n0 = blockIdx.x * BN;

  MmaCtx ctx;
  tf32_mainloop<(H_ * DH_), D_>(g_O, W, m0, n0, As, Bs, ctx);

  const int lane = threadIdx.x & 31;
  const int wid = threadIdx.x >> 5;
  const int wm = wid & 1, wn = wid >> 1;

#pragma unroll
  for (int nt = 0; nt < 4; nt++) {
    const int n = n0 + wn * 32 + nt * 8 + (lane & 3) * 2;
    const float bz0 = bias[n], bz1 = bias[n + 1];
#pragma unroll
    for (int mt = 0; mt < 4; mt++) {
      const int mbase = m0 + wm * 64 + mt * 16 + (lane >> 2);
#pragma unroll
      for (int half = 0; half < 2; half++) {
        const int m = mbase + half * 8;
        float2 v;
        v.x = ctx.acc[mt][nt][half * 2 + 0] + bz0;
        v.y = ctx.acc[mt][nt][half * 2 + 1] + bz1;
        *(float2*)&out[(size_t)m * D_ + n] = v;
      }
    }
  }
}

// ---------------------------------------------------------------------------
// Kernel 2: causal flash attention, fp32 (unchanged from passing round 1).
// ---------------------------------------------------------------------------
__global__ __launch_bounds__(256, 2) void attn_kernel() {
  __shared__ float QsT[64][64];   // QsT[e][i]
  __shared__ float KPs[64][64];   // phase 1: K^T[e][j]; phase 2: P[i][j]
  __shared__ float Vs[64][64];    // Vs[j][e]

  const int tid = threadIdx.x;
  const int tx = tid & 15, ty = tid >> 4;
  const int qt = blockIdx.x;
  const int bh = blockIdx.y;
  const int q0 = qt * 64;
  const int b = bh >> 4, h = bh & 15;

  const float* Qb = g_Q + (size_t)bh * S_ * DH_;
  const float* Kb = g_K + (size_t)bh * S_ * DH_;
  const float* Vb = g_V + (size_t)bh * S_ * DH_;

#pragma unroll
  for (int it = 0; it < 4; it++) {
    const int idx = tid + it * 256;
    const int j = idx & 63, e4 = idx >> 6;
    const float4 v = *(const float4*)&Qb[(q0 + j) * DH_ + e4 * 4];
    QsT[e4 * 4 + 0][j] = v.x;
    QsT[e4 * 4 + 1][j] = v.y;
    QsT[e4 * 4 + 2][j] = v.z;
    QsT[e4 * 4 + 3][j] = v.w;
  }

  const int i0 = ty * 4;
  const int j0 = tx * 4;
  const int e0 = tx * 4;

  float m_i[4], l_i[4], o[4][4];
#pragma unroll
  for (int i = 0; i < 4; i++) {
    m_i[i] = -1e30f;
    l_i[i] = 0.f;
#pragma unroll
    for (int e = 0; e < 4; e++) o[i][e] = 0.f;
  }

  for (int kt = 0; kt <= qt; kt++) {
    const int k0 = kt * 64;
    __syncthreads();
#pragma unroll
    for (int it = 0; it < 4; it++) {
      const int idx = tid + it * 256;
      const int j = idx & 63, e4 = idx >> 6;
      const float4 v = *(const float4*)&Kb[(k0 + j) * DH_ + e4 * 4];
      KPs[e4 * 4 + 0][j] = v.x;
      KPs[e4 * 4 + 1][j] = v.y;
      KPs[e4 * 4 + 2][j] = v.z;
      KPs[e4 * 4 + 3][j] = v.w;
      const int r = idx >> 4, c = (idx & 15) * 4;
      *(float4*)&Vs[r][c] = *(const float4*)&Vb[(k0 + r) * DH_ + c];
    }
    __syncthreads();

    float s[4][4];
#pragma unroll
    for (int i = 0; i < 4; i++)
#pragma unroll
      for (int j = 0; j < 4; j++) s[i][j] = 0.f;

#pragma unroll 8
    for (int e = 0; e < 64; e++) {
      const float4 qv = *(const float4*)&QsT[e][i0];
      const float4 kv = *(const float4*)&KPs[e][j0];
      const float qa[4] = {qv.x, qv.y, qv.z, qv.w};
      const float ka[4] = {kv.x, kv.y, kv.z, kv.w};
#pragma unroll
      for (int i = 0; i < 4; i++)
#pragma unroll
        for (int j = 0; j < 4; j++) s[i][j] += qa[i] * ka[j];
    }
#pragma unroll
    for (int i = 0; i < 4; i++)
#pragma unroll
      for (int j = 0; j < 4; j++) s[i][j] *= 0.125f;

    if (kt == qt) {
#pragma unroll
      for (int i = 0; i < 4; i++)
#pragma unroll
        for (int j = 0; j < 4; j++)
          if (j0 + j > i0 + i) s[i][j] = -1e30f;
    }

#pragma unroll
    for (int i = 0; i < 4; i++) {
      float mx = fmaxf(fmaxf(s[i][0], s[i][1]), fmaxf(s[i][2], s[i][3]));
#pragma unroll
      for (int off = 8; off; off >>= 1)
        mx = fmaxf(mx, __shfl_xor_sync(0xffffffffu, mx, off));
      const float mnew = fmaxf(m_i[i], mx);
      const float sc = __expf(m_i[i] - mnew);
      float rs = 0.f;
#pragma unroll
      for (int j = 0; j < 4; j++) {
        s[i][j] = __expf(s[i][j] - mnew);
        rs += s[i][j];
      }
#pragma unroll
      for (int off = 8; off; off >>= 1)
        rs += __shfl_xor_sync(0xffffffffu, rs, off);
      l_i[i] = l_i[i] * sc + rs;
      m_i[i] = mnew;
#pragma unroll
      for (int e = 0; e < 4; e++) o[i][e] *= sc;
    }

    __syncthreads();
#pragma unroll
    for (int i = 0; i < 4; i++)
      *(float4*)&KPs[i0 + i][j0] = make_float4(s[i][0], s[i][1], s[i][2], s[i][3]);
    __syncthreads();

#pragma unroll 8
    for (int j = 0; j < 64; j++) {
      const float4 vv = *(const float4*)&Vs[j][e0];
      const float va[4] = {vv.x, vv.y, vv.z, vv.w};
      float pr[4];
#pragma unroll
      for (int i = 0; i < 4; i++) pr[i] = KPs[i0 + i][j];
#pragma unroll
      for (int i = 0; i < 4; i++)
#pragma unroll
        for (int e = 0; e < 4; e++) o[i][e] += pr[i] * va[e];
    }
  }

#pragma unroll
  for (int i = 0; i < 4; i++) {
    const float inv = 1.f / l_i[i];
    const int srow = q0 + i0 + i;
    const float4 ov = make_float4(o[i][0] * inv, o[i][1] * inv,
                                  o[i][2] * inv, o[i][3] * inv);
    *(float4*)&g_O[(((size_t)(b * S_ + srow)) * H_ + h) * DH_ + e0] = ov;
  }
}

// ---------------------------------------------------------------------------
extern "C" void kernel_launch(void* const* d_in, const int* in_sizes, int n_in,
                              void* d_out, int out_size) {
  const float* x     = (const float*)d_in[0];  // [B,S,D]
  const float* w_qkv = (const float*)d_in[1];  // [D,3,H,DH]
  const float* b_qkv = (const float*)d_in[2];  // [3,H,DH]
  const float* w_out = (const float*)d_in[3];  // [H,DH,D]
  const float* b_out = (const float*)d_in[4];  // [D]
  float* out = (float*)d_out;                  // [B,S,D]

  qkv_gemm_kernel<<<dim3(NQKV / BN, M_ / BM), 256>>>(x, w_qkv, b_qkv);
  attn_kernel<<<dim3(S_ / 64, B_ * H_), 256>>>();
  out_gemm_kernel<<<dim3(D_ / BN, M_ / BM), 256>>>(w_out, b_out, out);
}

// round 5
// speedup vs baseline: 1.3919x; 1.1904x over previous
#include <cuda_runtime.h>
#include <cuda_bf16.h>
#include <cstdint>

// Problem constants
#define B_   4
#define S_   2048
#define D_   1024
#define H_   16
#define DH_  64
#define M_   (B_ * S_)       // 8192
#define NQKV (3 * D_)        // 3072

// GEMM tiling
#define BM 128
#define BN 128
#define BKT 16
#define ASTRIDE 20
#define BSTRIDE 136

// Attention smem strides
#define PSTR 68   // Ps/Q-stage row stride (floats)
#define KSTR 72   // KT/V row stride (floats)
#define ATTN_SMEM_FLOATS (128 * PSTR + 4 * 64 * KSTR)
#define ATTN_SMEM_BYTES (ATTN_SMEM_FLOATS * 4)

// Scratch (allocation-free rule: __device__ globals)
__device__ float g_Q[B_ * H_ * S_ * DH_];
__device__ float g_K[B_ * H_ * S_ * DH_];
__device__ float g_V[B_ * H_ * S_ * DH_];
__device__ float g_O[B_ * S_ * H_ * DH_];

__device__ __forceinline__ uint32_t smem_u32(const void* p) {
  return (uint32_t)__cvta_generic_to_shared(p);
}

__device__ __forceinline__ void cp_async16(uint32_t dst, const void* src) {
  asm volatile("cp.async.cg.shared.global [%0], [%1], 16;\n" ::"r"(dst), "l"(src));
}
__device__ __forceinline__ void cp_commit() {
  asm volatile("cp.async.commit_group;\n");
}
template <int N>
__device__ __forceinline__ void cp_wait() {
  asm volatile("cp.async.wait_group %0;\n" ::"n"(N));
}

__device__ __forceinline__ void ldmatrix_x4(uint32_t* r, uint32_t addr) {
  asm volatile(
      "ldmatrix.sync.aligned.m8n8.x4.shared.b16 {%0,%1,%2,%3}, [%4];\n"
      : "=r"(r[0]), "=r"(r[1]), "=r"(r[2]), "=r"(r[3])
      : "r"(addr));
}

__device__ __forceinline__ void mma_tf32(float* c, const uint32_t* a,
                                         uint32_t b0, uint32_t b1) {
  asm volatile(
      "mma.sync.aligned.m16n8k8.row.col.f32.tf32.tf32.f32 "
      "{%0,%1,%2,%3}, {%4,%5,%6,%7}, {%8,%9}, {%0,%1,%2,%3};\n"
      : "+f"(c[0]), "+f"(c[1]), "+f"(c[2]), "+f"(c[3])
      : "r"(a[0]), "r"(a[1]), "r"(a[2]), "r"(a[3]), "r"(b0), "r"(b1));
}

// 3xTF32 split: f = hi + lo with hi = rna_tf32(f), lo = rna_tf32(f - hi).
__device__ __forceinline__ void split_tf32(uint32_t fbits, uint32_t& hi,
                                           uint32_t& lo) {
  const float f = __uint_as_float(fbits);
  uint32_t h;
  asm("cvt.rna.tf32.f32 %0, %1;\n" : "=r"(h) : "f"(f));
  const float r = f - __uint_as_float(h);
  asm("cvt.rna.tf32.f32 %0, %1;\n" : "=r"(lo) : "f"(r));
  hi = h;
}
__device__ __forceinline__ void split_tf32f(float f, float& hi, float& lo) {
  uint32_t h, l;
  split_tf32(__float_as_uint(f), h, l);
  hi = __uint_as_float(h);
  lo = __uint_as_float(l);
}

// ---------------------------------------------------------------------------
// tf32x3 GEMM mainloop (unchanged from passing round)
// ---------------------------------------------------------------------------
struct MmaCtx {
  float acc[4][4][4];
};

template <int K, int N>
__device__ __forceinline__ void tf32_mainloop(
    const float* __restrict__ A, const float* __restrict__ Wm,
    int m0, int n0, float (*As)[BM * ASTRIDE], float (*Bs)[BKT * BSTRIDE],
    MmaCtx& ctx) {
  const int tid = threadIdx.x;
  const int lane = tid & 31;
  const int wid = tid >> 5;
  const int wm = wid & 1;
  const int wn = wid >> 1;

#pragma unroll
  for (int mt = 0; mt < 4; mt++)
#pragma unroll
    for (int nt = 0; nt < 4; nt++)
#pragma unroll
      for (int r = 0; r < 4; r++) ctx.acc[mt][nt][r] = 0.f;

  const int kTiles = K / BKT;

  const int acr0 = tid >> 2, akc0 = tid & 3;
  const int acr1 = (tid + 256) >> 2, akc1 = tid & 3;
  const int bk0 = tid >> 5, bnc = tid & 31;
  const int bk1 = (tid + 256) >> 5;

  auto load_tile = [&](int t, int buf) {
    const int k0 = t * BKT;
    cp_async16(smem_u32(&As[buf][acr0 * ASTRIDE + akc0 * 4]),
               A + (size_t)(m0 + acr0) * K + k0 + akc0 * 4);
    cp_async16(smem_u32(&As[buf][acr1 * ASTRIDE + akc1 * 4]),
               A + (size_t)(m0 + acr1) * K + k0 + akc1 * 4);
    cp_async16(smem_u32(&Bs[buf][bk0 * BSTRIDE + bnc * 4]),
               Wm + (size_t)(k0 + bk0) * N + n0 + bnc * 4);
    cp_async16(smem_u32(&Bs[buf][bk1 * BSTRIDE + bnc * 4]),
               Wm + (size_t)(k0 + bk1) * N + n0 + bnc * 4);
    cp_commit();
  };

  load_tile(0, 0);

  const int lrow = (lane & 7) + ((lane >> 3) & 1) * 8;
  const int lcol = ((lane >> 4) & 1) * 4;

  for (int t = 0; t < kTiles; t++) {
    const int buf = t & 1;
    if (t + 1 < kTiles) {
      load_tile(t + 1, (t + 1) & 1);
      cp_wait<1>();
    } else {
      cp_wait<0>();
    }
    __syncthreads();

#pragma unroll
    for (int ks = 0; ks < 2; ks++) {
      uint32_t ahi[4][4], alo[4][4];
#pragma unroll
      for (int mt = 0; mt < 4; mt++) {
        uint32_t af[4];
        const int row = wm * 64 + mt * 16 + lrow;
        ldmatrix_x4(af, smem_u32(&As[buf][row * ASTRIDE + ks * 8 + lcol]));
#pragma unroll
        for (int r = 0; r < 4; r++) split_tf32(af[r], ahi[mt][r], alo[mt][r]);
      }
      uint32_t bhi[4][2], blo[4][2];
#pragma unroll
      for (int nt = 0; nt < 4; nt++) {
        const int col = wn * 32 + nt * 8 + (lane >> 2);
        const int kr = ks * 8 + (lane & 3);
        split_tf32(__float_as_uint(Bs[buf][kr * BSTRIDE + col]),
                   bhi[nt][0], blo[nt][0]);
        split_tf32(__float_as_uint(Bs[buf][(kr + 4) * BSTRIDE + col]),
                   bhi[nt][1], blo[nt][1]);
      }
#pragma unroll
      for (int mt = 0; mt < 4; mt++)
#pragma unroll
        for (int nt = 0; nt < 4; nt++) {
          mma_tf32(ctx.acc[mt][nt], alo[mt], bhi[nt][0], bhi[nt][1]);
          mma_tf32(ctx.acc[mt][nt], ahi[mt], blo[nt][0], blo[nt][1]);
          mma_tf32(ctx.acc[mt][nt], ahi[mt], bhi[nt][0], bhi[nt][1]);
        }
    }
    __syncthreads();
  }
}

// ---------------------------------------------------------------------------
// Kernel 1: qkv = x @ w_qkv + b_qkv -> scatter to g_Q/g_K/g_V as [B,H,S,DH]
// ---------------------------------------------------------------------------
__global__ __launch_bounds__(256, 1) void qkv_gemm_kernel(
    const float* __restrict__ A, const float* __restrict__ W,
    const float* __restrict__ bias) {
  __shared__ float As[2][BM * ASTRIDE];
  __shared__ float Bs[2][BKT * BSTRIDE];
  const int m0 = blockIdx.y * BM;
  const int n0 = blockIdx.x * BN;

  MmaCtx ctx;
  tf32_mainloop<D_, NQKV>(A, W, m0, n0, As, Bs, ctx);

  const int lane = threadIdx.x & 31;
  const int wid = threadIdx.x >> 5;
  const int wm = wid & 1, wn = wid >> 1;

#pragma unroll
  for (int nt = 0; nt < 4; nt++) {
    const int n = n0 + wn * 32 + nt * 8 + (lane & 3) * 2;
    const int t = n >> 10;
    const int rem = n & 1023;
    const int h = rem >> 6;
    const int e = rem & 63;
    float* dst = (t == 0) ? g_Q : (t == 1) ? g_K : g_V;
    const float bz0 = bias[n], bz1 = bias[n + 1];
#pragma unroll
    for (int mt = 0; mt < 4; mt++) {
      const int mbase = m0 + wm * 64 + mt * 16 + (lane >> 2);
#pragma unroll
      for (int half = 0; half < 2; half++) {
        const int m = mbase + half * 8;
        const int b = m >> 11;
        const int s = m & 2047;
        float2 v;
        v.x = ctx.acc[mt][nt][half * 2 + 0] + bz0;
        v.y = ctx.acc[mt][nt][half * 2 + 1] + bz1;
        *(float2*)&dst[(((b * H_ + h) * S_ + s) * DH_) + e] = v;
      }
    }
  }
}

// ---------------------------------------------------------------------------
// Kernel 3: out = g_O @ w_out + b_out
// ---------------------------------------------------------------------------
__global__ __launch_bounds__(256, 1) void out_gemm_kernel(
    const float* __restrict__ W, const float* __restrict__ bias,
    float* __restrict__ out) {
  __shared__ float As[2][BM * ASTRIDE];
  __shared__ float Bs[2][BKT * BSTRIDE];
  const int m0 = blockIdx.y * BM;
  const int n0 = blockIdx.x * BN;

  MmaCtx ctx;
  tf32_mainloop<(H_ * DH_), D_>(g_O, W, m0, n0, As, Bs, ctx);

  const int lane = threadIdx.x & 31;
  const int wid = threadIdx.x >> 5;
  const int wm = wid & 1, wn = wid >> 1;

#pragma unroll
  for (int nt = 0; nt < 4; nt++) {
    const int n = n0 + wn * 32 + nt * 8 + (lane & 3) * 2;
    const float bz0 = bias[n], bz1 = bias[n + 1];
#pragma unroll
    for (int mt = 0; mt < 4; mt++) {
      const int mbase = m0 + wm * 64 + mt * 16 + (lane >> 2);
#pragma unroll
      for (int half = 0; half < 2; half++) {
        const int m = mbase + half * 8;
        float2 v;
        v.x = ctx.acc[mt][nt][half * 2 + 0] + bz0;
        v.y = ctx.acc[mt][nt][half * 2 + 1] + bz1;
        *(float2*)&out[(size_t)m * D_ + n] = v;
      }
    }
  }
}

// ---------------------------------------------------------------------------
// Kernel 2: causal flash attention on tensor cores (tf32x3 for S and PV).
// CTA = 128 q-rows of one (b,h). Warp w owns rows [w*16, w*16+16) x all cols.
// smem: Ps (Q-stage then P, warp-private rows) + KThi/KTlo + Vhi/Vlo.
// ---------------------------------------------------------------------------
__global__ __launch_bounds__(256, 1) void attn_kernel() {
  extern __shared__ float sm[];
  float* Ps   = sm;                      // 128 x PSTR (Q stage, then P)
  float* KThi = sm + 128 * PSTR;         // 64 x KSTR  (K^T hi: [e][j])
  float* KTlo = KThi + 64 * KSTR;
  float* Vhi  = KTlo + 64 * KSTR;        // 64 x KSTR  ([j][e])
  float* Vlo  = Vhi + 64 * KSTR;

  const int tid = threadIdx.x;
  const int lane = tid & 31;
  const int w = tid >> 5;
  const int g = lane >> 2;  // 0..7 (row group)
  const int t = lane & 3;   // 0..3
  const int qt = (int)gridDim.x - 1 - (int)blockIdx.x;  // long CTAs first
  const int q0 = qt * 128;
  const int bh = blockIdx.y;
  const int b = bh >> 4, h = bh & 15;

  const float* Qb = g_Q + (size_t)bh * S_ * DH_;
  const float* Kb = g_K + (size_t)bh * S_ * DH_;
  const float* Vb = g_V + (size_t)bh * S_ * DH_;

  // Stage Q tile (scaled by 1/sqrt(DH) = 0.125) into Ps.
#pragma unroll
  for (int it = 0; it < 8; it++) {
    const int idx = tid + it * 256;       // 2048 float4 chunks
    const int r = idx >> 4, c = (idx & 15) * 4;
    const float4 v = *(const float4*)&Qb[(q0 + r) * DH_ + c];
    float4 sv;
    sv.x = v.x * 0.125f; sv.y = v.y * 0.125f;
    sv.z = v.z * 0.125f; sv.w = v.w * 0.125f;
    *(float4*)&Ps[r * PSTR + c] = sv;
  }
  __syncthreads();

  // Load + split Q fragments once (Q reused across all k-tiles).
  const int lr = w * 16 + g;              // local row (this thread's row group)
  uint32_t qhi[8][4], qlo[8][4];
#pragma unroll
  for (int ks = 0; ks < 8; ks++) {
    const int c0 = ks * 8 + t;
    split_tf32(__float_as_uint(Ps[lr * PSTR + c0]),        qhi[ks][0], qlo[ks][0]);
    split_tf32(__float_as_uint(Ps[(lr + 8) * PSTR + c0]),  qhi[ks][1], qlo[ks][1]);
    split_tf32(__float_as_uint(Ps[lr * PSTR + c0 + 4]),    qhi[ks][2], qlo[ks][2]);
    split_tf32(__float_as_uint(Ps[(lr + 8) * PSTR + c0 + 4]), qhi[ks][3], qlo[ks][3]);
  }

  float m_a = -1e30f, m_b = -1e30f, l_a = 0.f, l_b = 0.f;
  float o[8][4];
#pragma unroll
  for (int nt = 0; nt < 8; nt++)
#pragma unroll
    for (int r = 0; r < 4; r++) o[nt][r] = 0.f;

  const int nkt = 2 * (qt + 1);
  for (int kt = 0; kt < nkt; kt++) {
    const int k0 = kt * 64;
    __syncthreads();  // prior-iter K/V reads done

    // Cooperative load + tf32-split of K (transposed) and V tiles.
#pragma unroll
    for (int it = 0; it < 4; it++) {
      const int idx = tid + it * 256;     // 1024 chunks
      // K: j varies across lanes -> conflict-free transposed scalar stores
      const int j = idx & 63, e4 = idx >> 6;
      const float4 kv = *(const float4*)&Kb[(k0 + j) * DH_ + e4 * 4];
      float h0, l0;
      split_tf32f(kv.x, h0, l0); KThi[(e4 * 4 + 0) * KSTR + j] = h0; KTlo[(e4 * 4 + 0) * KSTR + j] = l0;
      split_tf32f(kv.y, h0, l0); KThi[(e4 * 4 + 1) * KSTR + j] = h0; KTlo[(e4 * 4 + 1) * KSTR + j] = l0;
      split_tf32f(kv.z, h0, l0); KThi[(e4 * 4 + 2) * KSTR + j] = h0; KTlo[(e4 * 4 + 2) * KSTR + j] = l0;
      split_tf32f(kv.w, h0, l0); KThi[(e4 * 4 + 3) * KSTR + j] = h0; KTlo[(e4 * 4 + 3) * KSTR + j] = l0;
      // V: row-major
      const int vr = idx >> 4, vc = (idx & 15) * 4;
      const float4 vv = *(const float4*)&Vb[(k0 + vr) * DH_ + vc];
      float4 vh, vl;
      split_tf32f(vv.x, vh.x, vl.x);
      split_tf32f(vv.y, vh.y, vl.y);
      split_tf32f(vv.z, vh.z, vl.z);
      split_tf32f(vv.w, vh.w, vl.w);
      *(float4*)&Vhi[vr * KSTR + vc] = vh;
      *(float4*)&Vlo[vr * KSTR + vc] = vl;
    }
    __syncthreads();

    // S = Q K^T (tf32x3)
    float s[8][4];
#pragma unroll
    for (int nt = 0; nt < 8; nt++)
#pragma unroll
      for (int r = 0; r < 4; r++) s[nt][r] = 0.f;

#pragma unroll
    for (int ks = 0; ks < 8; ks++) {
      const int kr = ks * 8 + t;
#pragma unroll
      for (int nt = 0; nt < 8; nt++) {
        const int col = nt * 8 + g;
        const uint32_t b0h = __float_as_uint(KThi[kr * KSTR + col]);
        const uint32_t b1h = __float_as_uint(KThi[(kr + 4) * KSTR + col]);
        const uint32_t b0l = __float_as_uint(KTlo[kr * KSTR + col]);
        const uint32_t b1l = __float_as_uint(KTlo[(kr + 4) * KSTR + col]);
        mma_tf32(s[nt], qlo[ks], b0h, b1h);
        mma_tf32(s[nt], qhi[ks], b0l, b1l);
        mma_tf32(s[nt], qhi[ks], b0h, b1h);
      }
    }

    // Causal mask (only the two diagonal-adjacent tiles need it)
    if (kt >= nkt - 2) {
      const int ra = q0 + lr, rb = ra + 8;
#pragma unroll
      for (int nt = 0; nt < 8; nt++) {
        const int c0 = k0 + nt * 8 + t * 2;
        if (c0 > ra) s[nt][0] = -1e30f;
        if (c0 + 1 > ra) s[nt][1] = -1e30f;
        if (c0 > rb) s[nt][2] = -1e30f;
        if (c0 + 1 > rb) s[nt][3] = -1e30f;
      }
    }

    // Online softmax (rows warp-local: reduce over 4 lanes sharing a row)
    float mxa = -1e30f, mxb = -1e30f;
#pragma unroll
    for (int nt = 0; nt < 8; nt++) {
      mxa = fmaxf(mxa, fmaxf(s[nt][0], s[nt][1]));
      mxb = fmaxf(mxb, fmaxf(s[nt][2], s[nt][3]));
    }
#pragma unroll
    for (int off = 1; off <= 2; off <<= 1) {
      mxa = fmaxf(mxa, __shfl_xor_sync(0xffffffffu, mxa, off));
      mxb = fmaxf(mxb, __shfl_xor_sync(0xffffffffu, mxb, off));
    }
    const float mna = fmaxf(m_a, mxa), mnb = fmaxf(m_b, mxb);
    const float sca = __expf(m_a - mna), scb = __expf(m_b - mnb);
    float rsa = 0.f, rsb = 0.f;
#pragma unroll
    for (int nt = 0; nt < 8; nt++) {
      s[nt][0] = __expf(s[nt][0] - mna);
      s[nt][1] = __expf(s[nt][1] - mna);
      s[nt][2] = __expf(s[nt][2] - mnb);
      s[nt][3] = __expf(s[nt][3] - mnb);
      rsa += s[nt][0] + s[nt][1];
      rsb += s[nt][2] + s[nt][3];
    }
#pragma unroll
    for (int off = 1; off <= 2; off <<= 1) {
      rsa += __shfl_xor_sync(0xffffffffu, rsa, off);
      rsb += __shfl_xor_sync(0xffffffffu, rsb, off);
    }
    l_a = l_a * sca + rsa;
    l_b = l_b * scb + rsb;
    m_a = mna;
    m_b = mnb;
#pragma unroll
    for (int nt = 0; nt < 8; nt++) {
      o[nt][0] *= sca; o[nt][1] *= sca;
      o[nt][2] *= scb; o[nt][3] *= scb;
    }

    // P -> smem (warp-private rows; Ps buffer reuse is safe)
#pragma unroll
    for (int nt = 0; nt < 8; nt++) {
      *(float2*)&Ps[lr * PSTR + nt * 8 + t * 2] = make_float2(s[nt][0], s[nt][1]);
      *(float2*)&Ps[(lr + 8) * PSTR + nt * 8 + t * 2] = make_float2(s[nt][2], s[nt][3]);
    }
    __syncwarp();

    // O += P V (tf32x3)
#pragma unroll
    for (int ks = 0; ks < 8; ks++) {
      const int c0 = ks * 8 + t;
      uint32_t phi[4], plo[4];
      split_tf32(__float_as_uint(Ps[lr * PSTR + c0]),        phi[0], plo[0]);
      split_tf32(__float_as_uint(Ps[(lr + 8) * PSTR + c0]),  phi[1], plo[1]);
      split_tf32(__float_as_uint(Ps[lr * PSTR + c0 + 4]),    phi[2], plo[2]);
      split_tf32(__float_as_uint(Ps[(lr + 8) * PSTR + c0 + 4]), phi[3], plo[3]);
      const int kr = ks * 8 + t;
#pragma unroll
      for (int nt = 0; nt < 8; nt++) {
        const int col = nt * 8 + g;
        const uint32_t v0h = __float_as_uint(Vhi[kr * KSTR + col]);
        const uint32_t v1h = __float_as_uint(Vhi[(kr + 4) * KSTR + col]);
        const uint32_t v0l = __float_as_uint(Vlo[kr * KSTR + col]);
        const uint32_t v1l = __float_as_uint(Vlo[(kr + 4) * KSTR + col]);
        mma_tf32(o[nt], plo, v0h, v1h);
        mma_tf32(o[nt], phi, v0l, v1l);
        mma_tf32(o[nt], phi, v0h, v1h);
      }
    }
  }

  // Epilogue: normalize and store to g_O as [B,S,H,DH]
  const float ia = 1.f / l_a, ib = 1.f / l_b;
  const int ra = q0 + lr, rb = ra + 8;
#pragma unroll
  for (int nt = 0; nt < 8; nt++) {
    const int e = nt * 8 + t * 2;
    *(float2*)&g_O[(((size_t)(b * S_ + ra)) * H_ + h) * DH_ + e] =
        make_float2(o[nt][0] * ia, o[nt][1] * ia);
    *(float2*)&g_O[(((size_t)(b * S_ + rb)) * H_ + h) * DH_ + e] =
        make_float2(o[nt][2] * ib, o[nt][3] * ib);
  }
}

// ---------------------------------------------------------------------------
extern "C" void kernel_launch(void* const* d_in, const int* in_sizes, int n_in,
                              void* d_out, int out_size) {
  const float* x     = (const float*)d_in[0];  // [B,S,D]
  const float* w_qkv = (const float*)d_in[1];  // [D,3,H,DH]
  const float* b_qkv = (const float*)d_in[2];  // [3,H,DH]
  const float* w_out = (const float*)d_in[3];  // [H,DH,D]
  const float* b_out = (const float*)d_in[4];  // [D]
  float* out = (float*)d_out;                  // [B,S,D]

  cudaFuncSetAttribute(attn_kernel, cudaFuncAttributeMaxDynamicSharedMemorySize,
                       ATTN_SMEM_BYTES);

  qkv_gemm_kernel<<<dim3(NQKV / BN, M_ / BM), 256>>>(x, w_qkv, b_qkv);
  attn_kernel<<<dim3(S_ / 128, B_ * H_), 256, ATTN_SMEM_BYTES>>>();
  out_gemm_kernel<<<dim3(D_ / BN, M_ / BM), 256>>>(w_out, b_out, out);
}

// round 6
// speedup vs baseline: 1.7299x; 1.2429x over previous
#include <cuda_runtime.h>
#include <cuda_bf16.h>
#include <cstdint>

// Problem constants
#define B_   4
#define S_   2048
#define D_   1024
#define H_   16
#define DH_  64
#define M_   (B_ * S_)       // 8192
#define NQKV (3 * D_)        // 3072

// bf16x3 GEMM tiling
#define BM 128
#define BN 128
#define BK2 32               // k per tile (2 x k16 mma steps)
#define SASTR 36             // fp32 staging A row stride (floats)
#define SBSTR 132            // fp32 staging B row stride (floats)
#define AHSTR 40             // bf16 A plane row stride (bf16 elems) -> 80B
#define BHSTR 136            // bf16 B plane row stride (bf16 elems) -> 272B

// smem carve (bytes)
#define OFF_SA0 0
#define OFF_SA1 18432
#define OFF_SB0 36864
#define OFF_SB1 (36864 + 16896)
#define OFF_AH  70656
#define OFF_AL  80896
#define OFF_BH  91136
#define OFF_BL  99840
#define GEMM_SMEM_BYTES 108544

// Attention smem strides (tf32x3 attention, unchanged from passing round)
#define PSTR 68
#define KSTR 72
#define ATTN_SMEM_FLOATS (128 * PSTR + 4 * 64 * KSTR)
#define ATTN_SMEM_BYTES (ATTN_SMEM_FLOATS * 4)

// Scratch (allocation-free rule: __device__ globals)
__device__ float g_Q[B_ * H_ * S_ * DH_];
__device__ float g_K[B_ * H_ * S_ * DH_];
__device__ float g_V[B_ * H_ * S_ * DH_];
__device__ float g_O[B_ * S_ * H_ * DH_];

__device__ __forceinline__ uint32_t smem_u32(const void* p) {
  return (uint32_t)__cvta_generic_to_shared(p);
}

__device__ __forceinline__ void cp_async16(uint32_t dst, const void* src) {
  asm volatile("cp.async.cg.shared.global [%0], [%1], 16;\n" ::"r"(dst), "l"(src));
}
__device__ __forceinline__ void cp_commit() {
  asm volatile("cp.async.commit_group;\n");
}
template <int N>
__device__ __forceinline__ void cp_wait() {
  asm volatile("cp.async.wait_group %0;\n" ::"n"(N));
}

__device__ __forceinline__ void ldmatrix_x4(uint32_t* r, uint32_t addr) {
  asm volatile(
      "ldmatrix.sync.aligned.m8n8.x4.shared.b16 {%0,%1,%2,%3}, [%4];\n"
      : "=r"(r[0]), "=r"(r[1]), "=r"(r[2]), "=r"(r[3])
      : "r"(addr));
}
__device__ __forceinline__ void ldmatrix_x2_trans(uint32_t* r, uint32_t addr) {
  asm volatile(
      "ldmatrix.sync.aligned.m8n8.x2.trans.shared.b16 {%0,%1}, [%2];\n"
      : "=r"(r[0]), "=r"(r[1])
      : "r"(addr));
}

__device__ __forceinline__ void mma_bf16(float* c, const uint32_t* a,
                                         uint32_t b0, uint32_t b1) {
  asm volatile(
      "mma.sync.aligned.m16n8k16.row.col.f32.bf16.bf16.f32 "
      "{%0,%1,%2,%3}, {%4,%5,%6,%7}, {%8,%9}, {%0,%1,%2,%3};\n"
      : "+f"(c[0]), "+f"(c[1]), "+f"(c[2]), "+f"(c[3])
      : "r"(a[0]), "r"(a[1]), "r"(a[2]), "r"(a[3]), "r"(b0), "r"(b1));
}

__device__ __forceinline__ void mma_tf32(float* c, const uint32_t* a,
                                         uint32_t b0, uint32_t b1) {
  asm volatile(
      "mma.sync.aligned.m16n8k8.row.col.f32.tf32.tf32.f32 "
      "{%0,%1,%2,%3}, {%4,%5,%6,%7}, {%8,%9}, {%0,%1,%2,%3};\n"
      : "+f"(c[0]), "+f"(c[1]), "+f"(c[2]), "+f"(c[3])
      : "r"(a[0]), "r"(a[1]), "r"(a[2]), "r"(a[3]), "r"(b0), "r"(b1));
}

// bf16 split-pack: returns hi pair (f0 in low half, f1 in high), lo pair in out.
__device__ __forceinline__ uint32_t pack_split_bf16(float f0, float f1,
                                                    uint32_t& lo_out) {
  uint32_t hi;
  asm("cvt.rn.bf16x2.f32 %0, %1, %2;\n" : "=r"(hi) : "f"(f1), "f"(f0));
  const float h0 = __uint_as_float(hi << 16);
  const float h1 = __uint_as_float(hi & 0xFFFF0000u);
  const float l0 = f0 - h0;
  const float l1 = f1 - h1;
  asm("cvt.rn.bf16x2.f32 %0, %1, %2;\n" : "=r"(lo_out) : "f"(l1), "f"(l0));
  return hi;
}

// tf32 split (attention)
__device__ __forceinline__ void split_tf32(uint32_t fbits, uint32_t& hi,
                                           uint32_t& lo) {
  const float f = __uint_as_float(fbits);
  uint32_t h;
  asm("cvt.rna.tf32.f32 %0, %1;\n" : "=r"(h) : "f"(f));
  const float r = f - __uint_as_float(h);
  asm("cvt.rna.tf32.f32 %0, %1;\n" : "=r"(lo) : "f"(r));
  hi = h;
}
__device__ __forceinline__ void split_tf32f(float f, float& hi, float& lo) {
  uint32_t h, l;
  split_tf32(__float_as_uint(f), h, l);
  hi = __uint_as_float(h);
  lo = __uint_as_float(l);
}

// ---------------------------------------------------------------------------
// bf16x3 GEMM mainloop: 128x128 C tile, BK2=32 per iteration.
// A: [M][K] row-major fp32; Wm: [K][N] row-major fp32.
// ---------------------------------------------------------------------------
struct MmaCtx {
  float acc[4][4][4];
};

template <int K, int N>
__device__ __forceinline__ void bf16x3_mainloop(
    const float* __restrict__ A, const float* __restrict__ Wm,
    int m0, int n0, char* sm, MmaCtx& ctx) {
  float* SA[2] = {(float*)(sm + OFF_SA0), (float*)(sm + OFF_SA1)};
  float* SB[2] = {(float*)(sm + OFF_SB0), (float*)(sm + OFF_SB1)};
  uint32_t* Ah32 = (uint32_t*)(sm + OFF_AH);
  uint32_t* Al32 = (uint32_t*)(sm + OFF_AL);
  uint32_t* Bh32 = (uint32_t*)(sm + OFF_BH);
  uint32_t* Bl32 = (uint32_t*)(sm + OFF_BL);
  const uint32_t ahu = smem_u32(sm + OFF_AH);
  const uint32_t alu = smem_u32(sm + OFF_AL);
  const uint32_t bhu = smem_u32(sm + OFF_BH);
  const uint32_t blu = smem_u32(sm + OFF_BL);

  const int tid = threadIdx.x;
  const int lane = tid & 31;
  const int wid = tid >> 5;
  const int wm = wid & 1;
  const int wn = wid >> 1;

#pragma unroll
  for (int mt = 0; mt < 4; mt++)
#pragma unroll
    for (int nt = 0; nt < 4; nt++)
#pragma unroll
      for (int r = 0; r < 4; r++) ctx.acc[mt][nt][r] = 0.f;

  const int kTiles = K / BK2;

  auto load_stage = [&](int t, int buf) {
    const int k0 = t * BK2;
#pragma unroll
    for (int i = 0; i < 4; i++) {
      const int c = tid + i * 256;          // A: 1024 chunks of 16B
      const int row = c >> 3, kc = (c & 7) * 4;
      cp_async16(smem_u32(&SA[buf][row * SASTR + kc]),
                 A + (size_t)(m0 + row) * K + k0 + kc);
    }
#pragma unroll
    for (int i = 0; i < 4; i++) {
      const int c = tid + i * 256;          // B: 1024 chunks
      const int row = c >> 5, nc = (c & 31) * 4;
      cp_async16(smem_u32(&SB[buf][row * SBSTR + nc]),
                 Wm + (size_t)(k0 + row) * N + n0 + nc);
    }
    cp_commit();
  };

  load_stage(0, 0);

  const int lrow = lane & 15;
  const int lseg = (lane >> 4) * 8;         // A ldmatrix column segment (elems)

  for (int t = 0; t < kTiles; t++) {
    const int buf = t & 1;
    cp_wait<0>();
    __syncthreads();   // stage[buf] ready; prior mma reads of planes done

    // Convert: fp32 staging -> bf16 hi/lo planes (split once per element)
    float* SAb = SA[buf];
    float* SBb = SB[buf];
#pragma unroll
    for (int it = 0; it < 8; it++) {
      const int idx = tid + it * 256;       // A: 2048 pairs
      const int m = idx >> 4, kp = idx & 15;
      const float2 v = *(const float2*)&SAb[m * SASTR + kp * 2];
      uint32_t lo;
      const uint32_t hi = pack_split_bf16(v.x, v.y, lo);
      Ah32[m * 20 + kp] = hi;
      Al32[m * 20 + kp] = lo;
    }
#pragma unroll
    for (int it = 0; it < 8; it++) {
      const int idx = tid + it * 256;       // B: 2048 pairs
      const int k = idx >> 6, np = idx & 63;
      const float2 v = *(const float2*)&SBb[k * SBSTR + np * 2];
      uint32_t lo;
      const uint32_t hi = pack_split_bf16(v.x, v.y, lo);
      Bh32[k * 68 + np] = hi;
      Bl32[k * 68 + np] = lo;
    }
    if (t + 1 < kTiles) load_stage(t + 1, (t + 1) & 1);
    __syncthreads();   // planes ready

    // mma phase: 2 x k16 steps
#pragma unroll
    for (int ks = 0; ks < 2; ks++) {
      uint32_t ah[4][4], al[4][4];
#pragma unroll
      for (int mt = 0; mt < 4; mt++) {
        const int row = wm * 64 + mt * 16 + lrow;
        const uint32_t off = (uint32_t)(row * AHSTR + ks * 16 + lseg) * 2;
        ldmatrix_x4(ah[mt], ahu + off);
        ldmatrix_x4(al[mt], alu + off);
      }
      uint32_t bh[4][2], bl[4][2];
#pragma unroll
      for (int nt = 0; nt < 4; nt++) {
        const uint32_t off =
            (uint32_t)((ks * 16 + lrow) * BHSTR + wn * 32 + nt * 8) * 2;
        ldmatrix_x2_trans(bh[nt], bhu + off);
        ldmatrix_x2_trans(bl[nt], blu + off);
      }
#pragma unroll
      for (int mt = 0; mt < 4; mt++)
#pragma unroll
        for (int nt = 0; nt < 4; nt++) {
          mma_bf16(ctx.acc[mt][nt], al[mt], bh[nt][0], bh[nt][1]);
          mma_bf16(ctx.acc[mt][nt], ah[mt], bl[nt][0], bl[nt][1]);
          mma_bf16(ctx.acc[mt][nt], ah[mt], bh[nt][0], bh[nt][1]);
        }
    }
  }
}

// ---------------------------------------------------------------------------
// Kernel 1: qkv = x @ w_qkv + b_qkv -> scatter to g_Q/g_K/g_V as [B,H,S,DH]
// ---------------------------------------------------------------------------
__global__ __launch_bounds__(256, 1) void qkv_gemm_kernel(
    const float* __restrict__ A, const float* __restrict__ W,
    const float* __restrict__ bias) {
  extern __shared__ char sm[];
  const int m0 = blockIdx.y * BM;
  const int n0 = blockIdx.x * BN;

  MmaCtx ctx;
  bf16x3_mainloop<D_, NQKV>(A, W, m0, n0, sm, ctx);

  const int lane = threadIdx.x & 31;
  const int wid = threadIdx.x >> 5;
  const int wm = wid & 1, wn = wid >> 1;

#pragma unroll
  for (int nt = 0; nt < 4; nt++) {
    const int n = n0 + wn * 32 + nt * 8 + (lane & 3) * 2;
    const int t = n >> 10;
    const int rem = n & 1023;
    const int h = rem >> 6;
    const int e = rem & 63;
    float* dst = (t == 0) ? g_Q : (t == 1) ? g_K : g_V;
    const float bz0 = bias[n], bz1 = bias[n + 1];
#pragma unroll
    for (int mt = 0; mt < 4; mt++) {
      const int mbase = m0 + wm * 64 + mt * 16 + (lane >> 2);
#pragma unroll
      for (int half = 0; half < 2; half++) {
        const int m = mbase + half * 8;
        const int b = m >> 11;
        const int s = m & 2047;
        float2 v;
        v.x = ctx.acc[mt][nt][half * 2 + 0] + bz0;
        v.y = ctx.acc[mt][nt][half * 2 + 1] + bz1;
        *(float2*)&dst[(((b * H_ + h) * S_ + s) * DH_) + e] = v;
      }
    }
  }
}

// ---------------------------------------------------------------------------
// Kernel 3: out = g_O @ w_out + b_out
// ---------------------------------------------------------------------------
__global__ __launch_bounds__(256, 1) void out_gemm_kernel(
    const float* __restrict__ W, const float* __restrict__ bias,
    float* __restrict__ out) {
  extern __shared__ char sm[];
  const int m0 = blockIdx.y * BM;
  const int n0 = blockIdx.x * BN;

  MmaCtx ctx;
  bf16x3_mainloop<(H_ * DH_), D_>(g_O, W, m0, n0, sm, ctx);

  const int lane = threadIdx.x & 31;
  const int wid = threadIdx.x >> 5;
  const int wm = wid & 1, wn = wid >> 1;

#pragma unroll
  for (int nt = 0; nt < 4; nt++) {
    const int n = n0 + wn * 32 + nt * 8 + (lane & 3) * 2;
    const float bz0 = bias[n], bz1 = bias[n + 1];
#pragma unroll
    for (int mt = 0; mt < 4; mt++) {
      const int mbase = m0 + wm * 64 + mt * 16 + (lane >> 2);
#pragma unroll
      for (int half = 0; half < 2; half++) {
        const int m = mbase + half * 8;
        float2 v;
        v.x = ctx.acc[mt][nt][half * 2 + 0] + bz0;
        v.y = ctx.acc[mt][nt][half * 2 + 1] + bz1;
        *(float2*)&out[(size_t)m * D_ + n] = v;
      }
    }
  }
}

// ---------------------------------------------------------------------------
// Kernel 2: causal flash attention on tensor cores (tf32x3, unchanged).
// ---------------------------------------------------------------------------
__global__ __launch_bounds__(256, 1) void attn_kernel() {
  extern __shared__ float smf[];
  float* Ps   = smf;
  float* KThi = smf + 128 * PSTR;
  float* KTlo = KThi + 64 * KSTR;
  float* Vhi  = KTlo + 64 * KSTR;
  float* Vlo  = Vhi + 64 * KSTR;

  const int tid = threadIdx.x;
  const int lane = tid & 31;
  const int w = tid >> 5;
  const int g = lane >> 2;
  const int t = lane & 3;
  const int qt = (int)gridDim.x - 1 - (int)blockIdx.x;
  const int q0 = qt * 128;
  const int bh = blockIdx.y;
  const int b = bh >> 4, h = bh & 15;

  const float* Qb = g_Q + (size_t)bh * S_ * DH_;
  const float* Kb = g_K + (size_t)bh * S_ * DH_;
  const float* Vb = g_V + (size_t)bh * S_ * DH_;

#pragma unroll
  for (int it = 0; it < 8; it++) {
    const int idx = tid + it * 256;
    const int r = idx >> 4, c = (idx & 15) * 4;
    const float4 v = *(const float4*)&Qb[(q0 + r) * DH_ + c];
    float4 sv;
    sv.x = v.x * 0.125f; sv.y = v.y * 0.125f;
    sv.z = v.z * 0.125f; sv.w = v.w * 0.125f;
    *(float4*)&Ps[r * PSTR + c] = sv;
  }
  __syncthreads();

  const int lr = w * 16 + g;
  uint32_t qhi[8][4], qlo[8][4];
#pragma unroll
  for (int ks = 0; ks < 8; ks++) {
    const int c0 = ks * 8 + t;
    split_tf32(__float_as_uint(Ps[lr * PSTR + c0]),        qhi[ks][0], qlo[ks][0]);
    split_tf32(__float_as_uint(Ps[(lr + 8) * PSTR + c0]),  qhi[ks][1], qlo[ks][1]);
    split_tf32(__float_as_uint(Ps[lr * PSTR + c0 + 4]),    qhi[ks][2], qlo[ks][2]);
    split_tf32(__float_as_uint(Ps[(lr + 8) * PSTR + c0 + 4]), qhi[ks][3], qlo[ks][3]);
  }

  float m_a = -1e30f, m_b = -1e30f, l_a = 0.f, l_b = 0.f;
  float o[8][4];
#pragma unroll
  for (int nt = 0; nt < 8; nt++)
#pragma unroll
    for (int r = 0; r < 4; r++) o[nt][r] = 0.f;

  const int nkt = 2 * (qt + 1);
  for (int kt = 0; kt < nkt; kt++) {
    const int k0 = kt * 64;
    __syncthreads();

#pragma unroll
    for (int it = 0; it < 4; it++) {
      const int idx = tid + it * 256;
      const int j = idx & 63, e4 = idx >> 6;
      const float4 kv = *(const float4*)&Kb[(k0 + j) * DH_ + e4 * 4];
      float h0, l0;
      split_tf32f(kv.x, h0, l0); KThi[(e4 * 4 + 0) * KSTR + j] = h0; KTlo[(e4 * 4 + 0) * KSTR + j] = l0;
      split_tf32f(kv.y, h0, l0); KThi[(e4 * 4 + 1) * KSTR + j] = h0; KTlo[(e4 * 4 + 1) * KSTR + j] = l0;
      split_tf32f(kv.z, h0, l0); KThi[(e4 * 4 + 2) * KSTR + j] = h0; KTlo[(e4 * 4 + 2) * KSTR + j] = l0;
      split_tf32f(kv.w, h0, l0); KThi[(e4 * 4 + 3) * KSTR + j] = h0; KTlo[(e4 * 4 + 3) * KSTR + j] = l0;
      const int vr = idx >> 4, vc = (idx & 15) * 4;
      const float4 vv = *(const float4*)&Vb[(k0 + vr) * DH_ + vc];
      float4 vh, vl;
      split_tf32f(vv.x, vh.x, vl.x);
      split_tf32f(vv.y, vh.y, vl.y);
      split_tf32f(vv.z, vh.z, vl.z);
      split_tf32f(vv.w, vh.w, vl.w);
      *(float4*)&Vhi[vr * KSTR + vc] = vh;
      *(float4*)&Vlo[vr * KSTR + vc] = vl;
    }
    __syncthreads();

    float s[8][4];
#pragma unroll
    for (int nt = 0; nt < 8; nt++)
#pragma unroll
      for (int r = 0; r < 4; r++) s[nt][r] = 0.f;

#pragma unroll
    for (int ks = 0; ks < 8; ks++) {
      const int kr = ks * 8 + t;
#pragma unroll
      for (int nt = 0; nt < 8; nt++) {
        const int col = nt * 8 + g;
        const uint32_t b0h = __float_as_uint(KThi[kr * KSTR + col]);
        const uint32_t b1h = __float_as_uint(KThi[(kr + 4) * KSTR + col]);
        const uint32_t b0l = __float_as_uint(KTlo[kr * KSTR + col]);
        const uint32_t b1l = __float_as_uint(KTlo[(kr + 4) * KSTR + col]);
        mma_tf32(s[nt], qlo[ks], b0h, b1h);
        mma_tf32(s[nt], qhi[ks], b0l, b1l);
        mma_tf32(s[nt], qhi[ks], b0h, b1h);
      }
    }

    if (kt >= nkt - 2) {
      const int ra = q0 + lr, rb = ra + 8;
#pragma unroll
      for (int nt = 0; nt < 8; nt++) {
        const int c0 = k0 + nt * 8 + t * 2;
        if (c0 > ra) s[nt][0] = -1e30f;
        if (c0 + 1 > ra) s[nt][1] = -1e30f;
        if (c0 > rb) s[nt][2] = -1e30f;
        if (c0 + 1 > rb) s[nt][3] = -1e30f;
      }
    }

    float mxa = -1e30f, mxb = -1e30f;
#pragma unroll
    for (int nt = 0; nt < 8; nt++) {
      mxa = fmaxf(mxa, fmaxf(s[nt][0], s[nt][1]));
      mxb = fmaxf(mxb, fmaxf(s[nt][2], s[nt][3]));
    }
#pragma unroll
    for (int off = 1; off <= 2; off <<= 1) {
      mxa = fmaxf(mxa, __shfl_xor_sync(0xffffffffu, mxa, off));
      mxb = fmaxf(mxb, __shfl_xor_sync(0xffffffffu, mxb, off));
    }
    const float mna = fmaxf(m_a, mxa), mnb = fmaxf(m_b, mxb);
    const float sca = __expf(m_a - mna), scb = __expf(m_b - mnb);
    float rsa = 0.f, rsb = 0.f;
#pragma unroll
    for (int nt = 0; nt < 8; nt++) {
      s[nt][0] = __expf(s[nt][0] - mna);
      s[nt][1] = __expf(s[nt][1] - mna);
      s[nt][2] = __expf(s[nt][2] - mnb);
      s[nt][3] = __expf(s[nt][3] - mnb);
      rsa += s[nt][0] + s[nt][1];
      rsb += s[nt][2] + s[nt][3];
    }
#pragma unroll
    for (int off = 1; off <= 2; off <<= 1) {
      rsa += __shfl_xor_sync(0xffffffffu, rsa, off);
      rsb += __shfl_xor_sync(0xffffffffu, rsb, off);
    }
    l_a = l_a * sca + rsa;
    l_b = l_b * scb + rsb;
    m_a = mna;
    m_b = mnb;
#pragma unroll
    for (int nt = 0; nt < 8; nt++) {
      o[nt][0] *= sca; o[nt][1] *= sca;
      o[nt][2] *= scb; o[nt][3] *= scb;
    }

#pragma unroll
    for (int nt = 0; nt < 8; nt++) {
      *(float2*)&Ps[lr * PSTR + nt * 8 + t * 2] = make_float2(s[nt][0], s[nt][1]);
      *(float2*)&Ps[(lr + 8) * PSTR + nt * 8 + t * 2] = make_float2(s[nt][2], s[nt][3]);
    }
    __syncwarp();

#pragma unroll
    for (int ks = 0; ks < 8; ks++) {
      const int c0 = ks * 8 + t;
      uint32_t phi[4], plo[4];
      split_tf32(__float_as_uint(Ps[lr * PSTR + c0]),        phi[0], plo[0]);
      split_tf32(__float_as_uint(Ps[(lr + 8) * PSTR + c0]),  phi[1], plo[1]);
      split_tf32(__float_as_uint(Ps[lr * PSTR + c0 + 4]),    phi[2], plo[2]);
      split_tf32(__float_as_uint(Ps[(lr + 8) * PSTR + c0 + 4]), phi[3], plo[3]);
      const int kr = ks * 8 + t;
#pragma unroll
      for (int nt = 0; nt < 8; nt++) {
        const int col = nt * 8 + g;
        const uint32_t v0h = __float_as_uint(Vhi[kr * KSTR + col]);
        const uint32_t v1h = __float_as_uint(Vhi[(kr + 4) * KSTR + col]);
        const uint32_t v0l = __float_as_uint(Vlo[kr * KSTR + col]);
        const uint32_t v1l = __float_as_uint(Vlo[(kr + 4) * KSTR + col]);
        mma_tf32(o[nt], plo, v0h, v1h);
        mma_tf32(o[nt], phi, v0l, v1l);
        mma_tf32(o[nt], phi, v0h, v1h);
      }
    }
  }

  const float ia = 1.f / l_a, ib = 1.f / l_b;
  const int ra = q0 + lr, rb = ra + 8;
#pragma unroll
  for (int nt = 0; nt < 8; nt++) {
    const int e = nt * 8 + t * 2;
    *(float2*)&g_O[(((size_t)(b * S_ + ra)) * H_ + h) * DH_ + e] =
        make_float2(o[nt][0] * ia, o[nt][1] * ia);
    *(float2*)&g_O[(((size_t)(b * S_ + rb)) * H_ + h) * DH_ + e] =
        make_float2(o[nt][2] * ib, o[nt][3] * ib);
  }
}

// ---------------------------------------------------------------------------
extern "C" void kernel_launch(void* const* d_in, const int* in_sizes, int n_in,
                              void* d_out, int out_size) {
  const float* x     = (const float*)d_in[0];  // [B,S,D]
  const float* w_qkv = (const float*)d_in[1];  // [D,3,H,DH]
  const float* b_qkv = (const float*)d_in[2];  // [3,H,DH]
  const float* w_out = (const float*)d_in[3];  // [H,DH,D]
  const float* b_out = (const float*)d_in[4];  // [D]
  float* out = (float*)d_out;                  // [B,S,D]

  cudaFuncSetAttribute(qkv_gemm_kernel,
                       cudaFuncAttributeMaxDynamicSharedMemorySize,
                       GEMM_SMEM_BYTES);
  cudaFuncSetAttribute(out_gemm_kernel,
                       cudaFuncAttributeMaxDynamicSharedMemorySize,
                       GEMM_SMEM_BYTES);
  cudaFuncSetAttribute(attn_kernel, cudaFuncAttributeMaxDynamicSharedMemorySize,
                       ATTN_SMEM_BYTES);

  qkv_gemm_kernel<<<dim3(NQKV / BN, M_ / BM), 256, GEMM_SMEM_BYTES>>>(
      x, w_qkv, b_qkv);
  attn_kernel<<<dim3(S_ / 128, B_ * H_), 256, ATTN_SMEM_BYTES>>>();
  out_gemm_kernel<<<dim3(D_ / BN, M_ / BM), 256, GEMM_SMEM_BYTES>>>(
      w_out, b_out, out);
}

// round 7
// speedup vs baseline: 2.5358x; 1.4659x over previous
#include <cuda_runtime.h>
#include <cuda_bf16.h>
#include <cstdint>

// Problem constants
#define B_   4
#define S_   2048
#define D_   1024
#define H_   16
#define DH_  64
#define M_   (B_ * S_)       // 8192
#define NQKV (3 * D_)        // 3072
#define QKV_ELEMS (B_ * H_ * S_ * DH_)

// GEMM tiling (bf16-plane mainloop)
#define BM 128
#define BN 128
#define BK2 32
#define AHSTR 40             // A plane smem row stride (bf16)
#define BHSTR 136            // B plane smem row stride (bf16)
// smem: A: [buf][hi/lo] 128x40x2B = 10240 each; B: 32x136x2B = 8704 each
#define GEMM_SMEM_BYTES 75776

// Attention smem: Qh,Ql [128][72] bf16; Kh,Kl,Vh,Vl [64][72] bf16
#define QSTR 72
#define ATTN_SMEM_BYTES ((128 * QSTR * 2 + 4 * 64 * QSTR) * 2)

// Persistent bf16 hi/lo planes (allocation-free rule: __device__ globals)
__device__ __nv_bfloat16 g_Xh[M_ * D_], g_Xl[M_ * D_];
__device__ __nv_bfloat16 g_Wh[D_ * NQKV], g_Wl[D_ * NQKV];
__device__ __nv_bfloat16 g_WOh[D_ * D_], g_WOl[D_ * D_];
__device__ __nv_bfloat16 g_Qh[QKV_ELEMS], g_Ql[QKV_ELEMS];
__device__ __nv_bfloat16 g_Kh[QKV_ELEMS], g_Kl[QKV_ELEMS];
__device__ __nv_bfloat16 g_Vh[QKV_ELEMS], g_Vl[QKV_ELEMS];
__device__ __nv_bfloat16 g_Oh[QKV_ELEMS], g_Ol[QKV_ELEMS];

__device__ __forceinline__ uint32_t smem_u32(const void* p) {
  return (uint32_t)__cvta_generic_to_shared(p);
}
__device__ __forceinline__ void cp_async16(uint32_t dst, const void* src) {
  asm volatile("cp.async.cg.shared.global [%0], [%1], 16;\n" ::"r"(dst), "l"(src));
}
__device__ __forceinline__ void cp_commit() {
  asm volatile("cp.async.commit_group;\n");
}
template <int N>
__device__ __forceinline__ void cp_wait() {
  asm volatile("cp.async.wait_group %0;\n" ::"n"(N));
}

__device__ __forceinline__ void ldmatrix_x4(uint32_t* r, uint32_t addr) {
  asm volatile(
      "ldmatrix.sync.aligned.m8n8.x4.shared.b16 {%0,%1,%2,%3}, [%4];\n"
      : "=r"(r[0]), "=r"(r[1]), "=r"(r[2]), "=r"(r[3])
      : "r"(addr));
}
__device__ __forceinline__ void ldmatrix_x2(uint32_t* r, uint32_t addr) {
  asm volatile(
      "ldmatrix.sync.aligned.m8n8.x2.shared.b16 {%0,%1}, [%2];\n"
      : "=r"(r[0]), "=r"(r[1])
      : "r"(addr));
}
__device__ __forceinline__ void ldmatrix_x2_trans(uint32_t* r, uint32_t addr) {
  asm volatile(
      "ldmatrix.sync.aligned.m8n8.x2.trans.shared.b16 {%0,%1}, [%2];\n"
      : "=r"(r[0]), "=r"(r[1])
      : "r"(addr));
}

__device__ __forceinline__ void mma_bf16(float* c, const uint32_t* a,
                                         uint32_t b0, uint32_t b1) {
  asm volatile(
      "mma.sync.aligned.m16n8k16.row.col.f32.bf16.bf16.f32 "
      "{%0,%1,%2,%3}, {%4,%5,%6,%7}, {%8,%9}, {%0,%1,%2,%3};\n"
      : "+f"(c[0]), "+f"(c[1]), "+f"(c[2]), "+f"(c[3])
      : "r"(a[0]), "r"(a[1]), "r"(a[2]), "r"(a[3]), "r"(b0), "r"(b1));
}

// bf16 split-pack: hi pair returned (f0 low half), lo pair in lo_out.
__device__ __forceinline__ uint32_t pack_split_bf16(float f0, float f1,
                                                    uint32_t& lo_out) {
  uint32_t hi;
  asm("cvt.rn.bf16x2.f32 %0, %1, %2;\n" : "=r"(hi) : "f"(f1), "f"(f0));
  const float h0 = __uint_as_float(hi << 16);
  const float h1 = __uint_as_float(hi & 0xFFFF0000u);
  const float l0 = f0 - h0;
  const float l1 = f1 - h1;
  asm("cvt.rn.bf16x2.f32 %0, %1, %2;\n" : "=r"(lo_out) : "f"(l1), "f"(l0));
  return hi;
}

// ---------------------------------------------------------------------------
// Prepack: fp32 -> bf16 hi/lo planes. n2 = element pairs.
// ---------------------------------------------------------------------------
__global__ void split_kernel(const float* __restrict__ in,
                             __nv_bfloat16* __restrict__ hi,
                             __nv_bfloat16* __restrict__ lo) {
  const int i = blockIdx.x * blockDim.x + threadIdx.x;
  const float2 v = ((const float2*)in)[i];
  uint32_t l;
  const uint32_t h = pack_split_bf16(v.x, v.y, l);
  ((uint32_t*)hi)[i] = h;
  ((uint32_t*)lo)[i] = l;
}

// ---------------------------------------------------------------------------
// bf16x3 GEMM mainloop on prepacked planes. A: [M][K], B: [K][N].
// ---------------------------------------------------------------------------
struct MmaCtx {
  float acc[4][4][4];
};

template <int K, int N>
__device__ __forceinline__ void bf16_mainloop(
    const __nv_bfloat16* __restrict__ Ahp, const __nv_bfloat16* __restrict__ Alp,
    const __nv_bfloat16* __restrict__ Bhp, const __nv_bfloat16* __restrict__ Blp,
    int m0, int n0, char* sm, MmaCtx& ctx) {
  const int tid = threadIdx.x;
  const int lane = tid & 31;
  const int wid = tid >> 5;
  const int wm = wid & 1;
  const int wn = wid >> 1;

#pragma unroll
  for (int mt = 0; mt < 4; mt++)
#pragma unroll
    for (int nt = 0; nt < 4; nt++)
#pragma unroll
      for (int r = 0; r < 4; r++) ctx.acc[mt][nt][r] = 0.f;

  const int kTiles = K / BK2;
  const int ar0 = tid >> 2, akc = (tid & 3) * 8;
  const int ar1 = (tid + 256) >> 2;
  const int br0 = tid >> 4, bnc = (tid & 15) * 8;
  const int br1 = (tid + 256) >> 4;

  auto load_stage = [&](int t, int buf) {
    const int k0 = t * BK2;
    const uint32_t a_h = smem_u32(sm) + buf * 20480u;
    const uint32_t a_l = a_h + 10240u;
    const uint32_t b_h = smem_u32(sm) + 40960u + buf * 17408u;
    const uint32_t b_l = b_h + 8704u;
    cp_async16(a_h + (ar0 * AHSTR + akc) * 2, Ahp + (size_t)(m0 + ar0) * K + k0 + akc);
    cp_async16(a_h + (ar1 * AHSTR + akc) * 2, Ahp + (size_t)(m0 + ar1) * K + k0 + akc);
    cp_async16(a_l + (ar0 * AHSTR + akc) * 2, Alp + (size_t)(m0 + ar0) * K + k0 + akc);
    cp_async16(a_l + (ar1 * AHSTR + akc) * 2, Alp + (size_t)(m0 + ar1) * K + k0 + akc);
    cp_async16(b_h + (br0 * BHSTR + bnc) * 2, Bhp + (size_t)(k0 + br0) * N + n0 + bnc);
    cp_async16(b_h + (br1 * BHSTR + bnc) * 2, Bhp + (size_t)(k0 + br1) * N + n0 + bnc);
    cp_async16(b_l + (br0 * BHSTR + bnc) * 2, Blp + (size_t)(k0 + br0) * N + n0 + bnc);
    cp_async16(b_l + (br1 * BHSTR + bnc) * 2, Blp + (size_t)(k0 + br1) * N + n0 + bnc);
    cp_commit();
  };

  load_stage(0, 0);

  const int lrow = lane & 15;
  const int lseg = (lane >> 4) * 8;

  for (int t = 0; t < kTiles; t++) {
    const int buf = t & 1;
    if (t > 0) __syncthreads();           // all warps done with mma(t-1)
    if (t + 1 < kTiles) {
      load_stage(t + 1, buf ^ 1);
      cp_wait<1>();
    } else {
      cp_wait<0>();
    }
    __syncthreads();                      // buf t data visible to all

    const uint32_t ahu = smem_u32(sm) + buf * 20480u;
    const uint32_t alu = ahu + 10240u;
    const uint32_t bhu = smem_u32(sm) + 40960u + buf * 17408u;
    const uint32_t blu = bhu + 8704u;

#pragma unroll
    for (int ks = 0; ks < 2; ks++) {
      uint32_t ah[4][4], al[4][4];
#pragma unroll
      for (int mt = 0; mt < 4; mt++) {
        const int row = wm * 64 + mt * 16 + lrow;
        const uint32_t off = (uint32_t)(row * AHSTR + ks * 16 + lseg) * 2;
        ldmatrix_x4(ah[mt], ahu + off);
        ldmatrix_x4(al[mt], alu + off);
      }
      uint32_t bh[4][2], bl[4][2];
#pragma unroll
      for (int nt = 0; nt < 4; nt++) {
        const uint32_t off =
            (uint32_t)((ks * 16 + lrow) * BHSTR + wn * 32 + nt * 8) * 2;
        ldmatrix_x2_trans(bh[nt], bhu + off);
        ldmatrix_x2_trans(bl[nt], blu + off);
      }
#pragma unroll
      for (int mt = 0; mt < 4; mt++)
#pragma unroll
        for (int nt = 0; nt < 4; nt++) {
          mma_bf16(ctx.acc[mt][nt], al[mt], bh[nt][0], bh[nt][1]);
          mma_bf16(ctx.acc[mt][nt], ah[mt], bl[nt][0], bl[nt][1]);
          mma_bf16(ctx.acc[mt][nt], ah[mt], bh[nt][0], bh[nt][1]);
        }
    }
  }
}

// ---------------------------------------------------------------------------
// Kernel 1: qkv = x @ w_qkv + b_qkv -> bf16 hi/lo planes of Q(scaled),K,V
// ---------------------------------------------------------------------------
__global__ __launch_bounds__(256, 1) void qkv_gemm_kernel(
    const float* __restrict__ bias) {
  extern __shared__ char sm[];
  const int m0 = blockIdx.y * BM;
  const int n0 = blockIdx.x * BN;

  MmaCtx ctx;
  bf16_mainloop<D_, NQKV>(g_Xh, g_Xl, g_Wh, g_Wl, m0, n0, sm, ctx);

  const int lane = threadIdx.x & 31;
  const int wid = threadIdx.x >> 5;
  const int wm = wid & 1, wn = wid >> 1;

#pragma unroll
  for (int nt = 0; nt < 4; nt++) {
    const int n = n0 + wn * 32 + nt * 8 + (lane & 3) * 2;
    const int t = n >> 10;
    const int rem = n & 1023;
    const int h = rem >> 6;
    const int e = rem & 63;
    __nv_bfloat16* dh = (t == 0) ? g_Qh : (t == 1) ? g_Kh : g_Vh;
    __nv_bfloat16* dl = (t == 0) ? g_Ql : (t == 1) ? g_Kl : g_Vl;
    const float sc = (t == 0) ? 0.125f : 1.0f;
    const float bz0 = bias[n], bz1 = bias[n + 1];
#pragma unroll
    for (int mt = 0; mt < 4; mt++) {
      const int mbase = m0 + wm * 64 + mt * 16 + (lane >> 2);
#pragma unroll
      for (int half = 0; half < 2; half++) {
        const int m = mbase + half * 8;
        const int b = m >> 11;
        const int s = m & 2047;
        const float v0 = (ctx.acc[mt][nt][half * 2 + 0] + bz0) * sc;
        const float v1 = (ctx.acc[mt][nt][half * 2 + 1] + bz1) * sc;
        uint32_t lo;
        const uint32_t hi = pack_split_bf16(v0, v1, lo);
        const size_t idx = (((size_t)(b * H_ + h) * S_ + s) * DH_ + e) >> 1;
        ((uint32_t*)dh)[idx] = hi;
        ((uint32_t*)dl)[idx] = lo;
      }
    }
  }
}

// ---------------------------------------------------------------------------
// Kernel 3: out = O @ w_out + b_out (reads bf16 planes, writes fp32)
// ---------------------------------------------------------------------------
__global__ __launch_bounds__(256, 1) void out_gemm_kernel(
    const float* __restrict__ bias, float* __restrict__ out) {
  extern __shared__ char sm[];
  const int m0 = blockIdx.y * BM;
  const int n0 = blockIdx.x * BN;

  MmaCtx ctx;
  bf16_mainloop<D_, D_>(g_Oh, g_Ol, g_WOh, g_WOl, m0, n0, sm, ctx);

  const int lane = threadIdx.x & 31;
  const int wid = threadIdx.x >> 5;
  const int wm = wid & 1, wn = wid >> 1;

#pragma unroll
  for (int nt = 0; nt < 4; nt++) {
    const int n = n0 + wn * 32 + nt * 8 + (lane & 3) * 2;
    const float bz0 = bias[n], bz1 = bias[n + 1];
#pragma unroll
    for (int mt = 0; mt < 4; mt++) {
      const int mbase = m0 + wm * 64 + mt * 16 + (lane >> 2);
#pragma unroll
      for (int half = 0; half < 2; half++) {
        const int m = mbase + half * 8;
        float2 v;
        v.x = ctx.acc[mt][nt][half * 2 + 0] + bz0;
        v.y = ctx.acc[mt][nt][half * 2 + 1] + bz1;
        *(float2*)&out[(size_t)m * D_ + n] = v;
      }
    }
  }
}

// ---------------------------------------------------------------------------
// Kernel 2: causal flash attention, fully bf16x3, P in registers (FA2-style).
// CTA = 128 q-rows of one (b,h); warp w owns rows [w*16, w*16+16).
// ---------------------------------------------------------------------------
__global__ __launch_bounds__(256, 1) void attn_kernel() {
  extern __shared__ char smc[];
  __nv_bfloat16* Qh = (__nv_bfloat16*)smc;                  // [128][QSTR]
  __nv_bfloat16* Ql = Qh + 128 * QSTR;
  __nv_bfloat16* Kh = Ql + 128 * QSTR;                      // [64][QSTR]
  __nv_bfloat16* Kl = Kh + 64 * QSTR;
  __nv_bfloat16* Vh = Kl + 64 * QSTR;
  __nv_bfloat16* Vl = Vh + 64 * QSTR;
  const uint32_t qh_u = smem_u32(Qh), ql_u = smem_u32(Ql);
  const uint32_t kh_u = smem_u32(Kh), kl_u = smem_u32(Kl);
  const uint32_t vh_u = smem_u32(Vh), vl_u = smem_u32(Vl);

  const int tid = threadIdx.x;
  const int lane = tid & 31;
  const int w = tid >> 5;
  const int g = lane >> 2;
  const int t = lane & 3;
  const int qt = (int)gridDim.x - 1 - (int)blockIdx.x;  // long CTAs first
  const int q0 = qt * 128;
  const int bh = blockIdx.y;
  const int b = bh >> 4, h = bh & 15;
  const size_t base = (size_t)bh * S_ * DH_;

  // Stage Q planes (already scaled by 0.125 at qkv epilogue)
#pragma unroll
  for (int it = 0; it < 8; it++) {
    const int idx = tid + it * 256;       // 2048 chunks of 16B
    const int pl = idx >> 10;             // 0: hi, 1: lo
    const int r = (idx >> 3) & 127, c = (idx & 7) * 8;
    const __nv_bfloat16* src = pl ? g_Ql : g_Qh;
    __nv_bfloat16* dst = pl ? Ql : Qh;
    *(uint4*)&dst[r * QSTR + c] = *(const uint4*)&src[base + (size_t)(q0 + r) * DH_ + c];
  }
  __syncthreads();

  // Q fragments (held in registers across all k-tiles)
  uint32_t qfh[4][4], qfl[4][4];
  {
    const int row = w * 16 + (lane & 15);
    const int seg = (lane >> 4) * 8;
#pragma unroll
    for (int ks = 0; ks < 4; ks++) {
      const uint32_t off = (uint32_t)(row * QSTR + ks * 16 + seg) * 2;
      ldmatrix_x4(qfh[ks], qh_u + off);
      ldmatrix_x4(qfl[ks], ql_u + off);
    }
  }

  float m_a = -1e30f, m_b = -1e30f, l_a = 0.f, l_b = 0.f;
  float o[8][4];
#pragma unroll
  for (int nt = 0; nt < 8; nt++)
#pragma unroll
    for (int r = 0; r < 4; r++) o[nt][r] = 0.f;

  const int nkt = 2 * (qt + 1);
  for (int kt = 0; kt < nkt; kt++) {
    const int k0 = kt * 64;
    __syncthreads();  // prior-iter K/V reads done

    // Copy K/V bf16 planes into smem (4 planes x 64x64)
#pragma unroll
    for (int it = 0; it < 8; it++) {
      const int idx = tid + it * 256;     // 2048 chunks
      const int pl = idx >> 9;            // 0:Kh 1:Kl 2:Vh 3:Vl
      const int r = (idx >> 3) & 63, c = (idx & 7) * 8;
      const __nv_bfloat16* src = (pl == 0) ? g_Kh : (pl == 1) ? g_Kl
                               : (pl == 2) ? g_Vh : g_Vl;
      __nv_bfloat16* dst = (pl == 0) ? Kh : (pl == 1) ? Kl
                          : (pl == 2) ? Vh : Vl;
      *(uint4*)&dst[r * QSTR + c] = *(const uint4*)&src[base + (size_t)(k0 + r) * DH_ + c];
    }
    __syncthreads();

    // S = Q K^T (bf16x3). B frag: K rows are n, non-trans ldmatrix.
    float s[8][4];
#pragma unroll
    for (int nt = 0; nt < 8; nt++) {
#pragma unroll
      for (int r = 0; r < 4; r++) s[nt][r] = 0.f;
      const uint32_t roff =
          (uint32_t)((nt * 8 + (lane & 7)) * QSTR + ((lane >> 3) & 1) * 8) * 2;
#pragma unroll
      for (int ks = 0; ks < 4; ks++) {
        uint32_t kbh[2], kbl[2];
        const uint32_t off = roff + (uint32_t)(ks * 16) * 2;
        ldmatrix_x2(kbh, kh_u + off);
        ldmatrix_x2(kbl, kl_u + off);
        mma_bf16(s[nt], qfl[ks], kbh[0], kbh[1]);
        mma_bf16(s[nt], qfh[ks], kbl[0], kbl[1]);
        mma_bf16(s[nt], qfh[ks], kbh[0], kbh[1]);
      }
    }

    const int lr = w * 16 + g;
    // Causal mask (diagonal-adjacent tiles only)
    if (kt >= nkt - 2) {
      const int ra = q0 + lr, rb = ra + 8;
#pragma unroll
      for (int nt = 0; nt < 8; nt++) {
        const int c0 = k0 + nt * 8 + t * 2;
        if (c0 > ra) s[nt][0] = -1e30f;
        if (c0 + 1 > ra) s[nt][1] = -1e30f;
        if (c0 > rb) s[nt][2] = -1e30f;
        if (c0 + 1 > rb) s[nt][3] = -1e30f;
      }
    }

    // Online softmax (row groups = 4 lanes)
    float mxa = -1e30f, mxb = -1e30f;
#pragma unroll
    for (int nt = 0; nt < 8; nt++) {
      mxa = fmaxf(mxa, fmaxf(s[nt][0], s[nt][1]));
      mxb = fmaxf(mxb, fmaxf(s[nt][2], s[nt][3]));
    }
#pragma unroll
    for (int off = 1; off <= 2; off <<= 1) {
      mxa = fmaxf(mxa, __shfl_xor_sync(0xffffffffu, mxa, off));
      mxb = fmaxf(mxb, __shfl_xor_sync(0xffffffffu, mxb, off));
    }
    const float mna = fmaxf(m_a, mxa), mnb = fmaxf(m_b, mxb);
    const float sca = __expf(m_a - mna), scb = __expf(m_b - mnb);
    float rsa = 0.f, rsb = 0.f;
#pragma unroll
    for (int nt = 0; nt < 8; nt++) {
      s[nt][0] = __expf(s[nt][0] - mna);
      s[nt][1] = __expf(s[nt][1] - mna);
      s[nt][2] = __expf(s[nt][2] - mnb);
      s[nt][3] = __expf(s[nt][3] - mnb);
      rsa += s[nt][0] + s[nt][1];
      rsb += s[nt][2] + s[nt][3];
    }
#pragma unroll
    for (int off = 1; off <= 2; off <<= 1) {
      rsa += __shfl_xor_sync(0xffffffffu, rsa, off);
      rsb += __shfl_xor_sync(0xffffffffu, rsb, off);
    }
    l_a = l_a * sca + rsa;
    l_b = l_b * scb + rsb;
    m_a = mna;
    m_b = mnb;
#pragma unroll
    for (int nt = 0; nt < 8; nt++) {
      o[nt][0] *= sca; o[nt][1] *= sca;
      o[nt][2] *= scb; o[nt][3] *= scb;
    }

    // O += P V: P C-frag == A-frag (FA2). Split P to bf16 hi/lo in regs.
#pragma unroll
    for (int jt = 0; jt < 4; jt++) {
      uint32_t ph[4], pl[4];
      ph[0] = pack_split_bf16(s[2 * jt][0], s[2 * jt][1], pl[0]);
      ph[1] = pack_split_bf16(s[2 * jt][2], s[2 * jt][3], pl[1]);
      ph[2] = pack_split_bf16(s[2 * jt + 1][0], s[2 * jt + 1][1], pl[2]);
      ph[3] = pack_split_bf16(s[2 * jt + 1][2], s[2 * jt + 1][3], pl[3]);
      const uint32_t roff = (uint32_t)((jt * 16 + (lane & 15)) * QSTR) * 2;
#pragma unroll
      for (int nt = 0; nt < 8; nt++) {
        uint32_t vbh[2], vbl[2];
        const uint32_t off = roff + (uint32_t)(nt * 8) * 2;
        ldmatrix_x2_trans(vbh, vh_u + off);
        ldmatrix_x2_trans(vbl, vl_u + off);
        mma_bf16(o[nt], pl, vbh[0], vbh[1]);
        mma_bf16(o[nt], ph, vbl[0], vbl[1]);
        mma_bf16(o[nt], ph, vbh[0], vbh[1]);
      }
    }
  }

  // Epilogue: normalize, split to bf16 hi/lo O planes [B,S,H,DH]
  const float ia = 1.f / l_a, ib = 1.f / l_b;
  const int lr = w * 16 + g;
  const int ra = q0 + lr, rb = ra + 8;
#pragma unroll
  for (int nt = 0; nt < 8; nt++) {
    const int e = nt * 8 + t * 2;
    uint32_t lo;
    uint32_t hi = pack_split_bf16(o[nt][0] * ia, o[nt][1] * ia, lo);
    size_t idx = (((size_t)(b * S_ + ra) * H_ + h) * DH_ + e) >> 1;
    ((uint32_t*)g_Oh)[idx] = hi;
    ((uint32_t*)g_Ol)[idx] = lo;
    hi = pack_split_bf16(o[nt][2] * ib, o[nt][3] * ib, lo);
    idx = (((size_t)(b * S_ + rb) * H_ + h) * DH_ + e) >> 1;
    ((uint32_t*)g_Oh)[idx] = hi;
    ((uint32_t*)g_Ol)[idx] = lo;
  }
}

// ---------------------------------------------------------------------------
extern "C" void kernel_launch(void* const* d_in, const int* in_sizes, int n_in,
                              void* d_out, int out_size) {
  const float* x     = (const float*)d_in[0];  // [B,S,D]
  const float* w_qkv = (const float*)d_in[1];  // [D,3,H,DH]
  const float* b_qkv = (const float*)d_in[2];  // [3,H,DH]
  const float* w_out = (const float*)d_in[3];  // [H,DH,D]
  const float* b_out = (const float*)d_in[4];  // [D]
  float* out = (float*)d_out;                  // [B,S,D]

  cudaFuncSetAttribute(qkv_gemm_kernel,
                       cudaFuncAttributeMaxDynamicSharedMemorySize,
                       GEMM_SMEM_BYTES);
  cudaFuncSetAttribute(out_gemm_kernel,
                       cudaFuncAttributeMaxDynamicSharedMemorySize,
                       GEMM_SMEM_BYTES);
  cudaFuncSetAttribute(attn_kernel, cudaFuncAttributeMaxDynamicSharedMemorySize,
                       ATTN_SMEM_BYTES);

  __nv_bfloat16 *xh, *xl, *wh, *wl, *woh, *wol;
  cudaGetSymbolAddress((void**)&xh, g_Xh);
  cudaGetSymbolAddress((void**)&xl, g_Xl);
  cudaGetSymbolAddress((void**)&wh, g_Wh);
  cudaGetSymbolAddress((void**)&wl, g_Wl);
  cudaGetSymbolAddress((void**)&woh, g_WOh);
  cudaGetSymbolAddress((void**)&wol, g_WOl);

  split_kernel<<<(M_ * D_ / 2) / 256, 256>>>(x, xh, xl);
  split_kernel<<<(D_ * NQKV / 2) / 256, 256>>>(w_qkv, wh, wl);
  split_kernel<<<(D_ * D_ / 2) / 256, 256>>>(w_out, woh, wol);

  qkv_gemm_kernel<<<dim3(NQKV / BN, M_ / BM), 256, GEMM_SMEM_BYTES>>>(b_qkv);
  attn_kernel<<<dim3(S_ / 128, B_ * H_), 256, ATTN_SMEM_BYTES>>>();
  out_gemm_kernel<<<dim3(D_ / BN, M_ / BM), 256, GEMM_SMEM_BYTES>>>(b_out, out);
}